// round 4
// baseline (speedup 1.0000x reference)
#include <cuda_runtime.h>
#include <cuda_fp16.h>
#include <stdint.h>
#include <math.h>

// Problem constants
#define Bb 128
#define NQ 256
#define NC 128
#define D  1024
#define AD 256   // attn_dim
#define HD 128   // attn_dim/2
#define MD 512   // 2*attn_dim

// ---------------- scratch (device globals: no runtime allocation) ----------------
__device__ float g_S[Bb * NC * NQ];
__device__ float g_invn[Bb * NC];
__device__ float g_attn[Bb * NQ * NC];
__device__ float g_wc[Bb * NQ * D];
__device__ float g_matrix[Bb * NQ * D];
__device__ float g_smooth[Bb * NQ];
__device__ float g_common[Bb * NQ * AD];
__device__ float g_h1[Bb * NQ * MD];
__device__ float g_sh[Bb * NQ * HD];

// ---------------- utils ----------------
__device__ __forceinline__ float warp_sum(float v) {
#pragma unroll
    for (int o = 16; o > 0; o >>= 1) v += __shfl_xor_sync(0xffffffffu, v, o);
    return v;
}

__device__ __forceinline__ uint32_t pack2(float a, float b) {
    __half2 h = __floats2half2_rn(a, b);
    return *(uint32_t*)&h;
}

__device__ __forceinline__ void mma_f16(float* c, const uint32_t* a, const uint32_t* b) {
    asm volatile(
        "mma.sync.aligned.m16n8k16.row.col.f32.f16.f16.f32 "
        "{%0,%1,%2,%3},{%4,%5,%6,%7},{%8,%9},{%0,%1,%2,%3};"
        : "+f"(c[0]), "+f"(c[1]), "+f"(c[2]), "+f"(c[3])
        : "r"(a[0]), "r"(a[1]), "r"(a[2]), "r"(a[3]), "r"(b[0]), "r"(b[1]));
}

// smem stride in halves (32 data + 8 pad -> conflict-free frag loads)
#define KS 40

// ---------------- unified fp16 tensor-core GEMM ----------------
// Block tile 128(M) x 128(N), K chunks of 32, 8 warps (4M x 2N), warp tile 32x64.
// AM: 0 plain A[m][k];  1 A = (A - A2)^2
// BM: 1 B[n][k] = Bsrc[n][k] * Mx[n][k]  (k-major rows)
//     2 B[n][k] = Bsrc[k*ldn + n]         (row-major weight, transposed load)
// EPI: 0 leaky-relu store; 1 plain store; 2 +bias store; 3 +bias tanh store;
//      4 matrix-update: extra = clip(tanh(v+bias)+extra, -1, 1)
template<int AM, int BM, int EPI>
__global__ void __launch_bounds__(256) hgemm(
    const float* __restrict__ Ap, const float* __restrict__ A2p,
    const float* __restrict__ Bsrc, const float* __restrict__ Mxp,
    const float* __restrict__ bias, float* __restrict__ Cp,
    float* __restrict__ extra,
    int K, int ldn, int ldc, size_t sA, size_t sB, size_t sC)
{
    __shared__ __half As[2][128 * KS];
    __shared__ __half Bs[2][128 * KS];

    const int tid  = threadIdx.x;
    const int warp = tid >> 5, lane = tid & 31;
    const int g = lane >> 2, tg = lane & 3;
    const int wm = (warp & 3) * 32;
    const int wn = (warp >> 2) * 64;

    const int z  = blockIdx.z;
    const int m0 = blockIdx.y * 128;
    const int n0 = blockIdx.x * 128;

    const float* A  = Ap + (size_t)z * sA;
    const float* A2 = (AM == 1) ? (A2p + (size_t)z * sA) : nullptr;
    const float* Bp = Bsrc + (size_t)z * sB;
    const float* Mx = (BM == 1) ? (Mxp + (size_t)z * sB) : nullptr;
    float* C = Cp ? (Cp + (size_t)z * sC) : nullptr;

    // load mappings
    const int row  = tid & 127;      // m (or n for BM==1)
    const int half = tid >> 7;       // k sub-block 0..15 / 16..31
    const int kk2  = tid >> 3;       // BM==2: k row 0..31
    const int ngrp = (tid & 7) * 16; // BM==2: n group

    float acc[2][8][4];
#pragma unroll
    for (int i = 0; i < 2; i++)
#pragma unroll
        for (int j = 0; j < 8; j++)
#pragma unroll
            for (int r = 0; r < 4; r++) acc[i][j][r] = 0.0f;

    const int NCH = K >> 5;
    float aA[16], aB[16];

    // ---- prefetch chunk 0 ----
    {
        const float* src = A + (size_t)(m0 + row) * K + half * 16;
#pragma unroll
        for (int c = 0; c < 4; c++) {
            float4 v = *(const float4*)(src + c * 4);
            if (AM == 1) {
                float4 w = *(const float4*)(A2 + (size_t)(m0 + row) * K + half * 16 + c * 4);
                v.x -= w.x; v.y -= w.y; v.z -= w.z; v.w -= w.w;
                v.x *= v.x; v.y *= v.y; v.z *= v.z; v.w *= v.w;
            }
            aA[c * 4 + 0] = v.x; aA[c * 4 + 1] = v.y; aA[c * 4 + 2] = v.z; aA[c * 4 + 3] = v.w;
        }
        if (BM == 1) {
            const float* qs = Bp + (size_t)(n0 + row) * K + half * 16;
            const float* ms = Mx + (size_t)(n0 + row) * K + half * 16;
#pragma unroll
            for (int c = 0; c < 4; c++) {
                float4 q = *(const float4*)(qs + c * 4);
                float4 m = *(const float4*)(ms + c * 4);
                aB[c * 4 + 0] = q.x * m.x; aB[c * 4 + 1] = q.y * m.y;
                aB[c * 4 + 2] = q.z * m.z; aB[c * 4 + 3] = q.w * m.w;
            }
        } else {
            const float* src2 = Bp + (size_t)kk2 * ldn + n0 + ngrp;
#pragma unroll
            for (int c = 0; c < 4; c++) {
                float4 v = *(const float4*)(src2 + c * 4);
                aB[c * 4 + 0] = v.x; aB[c * 4 + 1] = v.y; aB[c * 4 + 2] = v.z; aB[c * 4 + 3] = v.w;
            }
        }
    }

    for (int i = 0; i < NCH; i++) {
        const int s = i & 1;

        // ---- store prefetched regs to smem stage s ----
        {
            uint4 u0, u1;
            u0.x = pack2(aA[0], aA[1]);  u0.y = pack2(aA[2], aA[3]);
            u0.z = pack2(aA[4], aA[5]);  u0.w = pack2(aA[6], aA[7]);
            u1.x = pack2(aA[8], aA[9]);  u1.y = pack2(aA[10], aA[11]);
            u1.z = pack2(aA[12], aA[13]); u1.w = pack2(aA[14], aA[15]);
            *(uint4*)&As[s][row * KS + half * 16]     = u0;
            *(uint4*)&As[s][row * KS + half * 16 + 8] = u1;

            if (BM == 1) {
                uint4 v0, v1;
                v0.x = pack2(aB[0], aB[1]);  v0.y = pack2(aB[2], aB[3]);
                v0.z = pack2(aB[4], aB[5]);  v0.w = pack2(aB[6], aB[7]);
                v1.x = pack2(aB[8], aB[9]);  v1.y = pack2(aB[10], aB[11]);
                v1.z = pack2(aB[12], aB[13]); v1.w = pack2(aB[14], aB[15]);
                *(uint4*)&Bs[s][row * KS + half * 16]     = v0;
                *(uint4*)&Bs[s][row * KS + half * 16 + 8] = v1;
            } else {
#pragma unroll
                for (int j = 0; j < 16; j++)
                    Bs[s][(ngrp + j) * KS + kk2] = __float2half_rn(aB[j]);
            }
        }
        __syncthreads();

        // ---- prefetch chunk i+1 (overlaps MMA below) ----
        if (i + 1 < NCH) {
            const int k0 = (i + 1) * 32;
            const float* src = A + (size_t)(m0 + row) * K + k0 + half * 16;
#pragma unroll
            for (int c = 0; c < 4; c++) {
                float4 v = *(const float4*)(src + c * 4);
                if (AM == 1) {
                    float4 w = *(const float4*)(A2 + (size_t)(m0 + row) * K + k0 + half * 16 + c * 4);
                    v.x -= w.x; v.y -= w.y; v.z -= w.z; v.w -= w.w;
                    v.x *= v.x; v.y *= v.y; v.z *= v.z; v.w *= v.w;
                }
                aA[c * 4 + 0] = v.x; aA[c * 4 + 1] = v.y; aA[c * 4 + 2] = v.z; aA[c * 4 + 3] = v.w;
            }
            if (BM == 1) {
                const float* qs = Bp + (size_t)(n0 + row) * K + k0 + half * 16;
                const float* ms = Mx + (size_t)(n0 + row) * K + k0 + half * 16;
#pragma unroll
                for (int c = 0; c < 4; c++) {
                    float4 q = *(const float4*)(qs + c * 4);
                    float4 m = *(const float4*)(ms + c * 4);
                    aB[c * 4 + 0] = q.x * m.x; aB[c * 4 + 1] = q.y * m.y;
                    aB[c * 4 + 2] = q.z * m.z; aB[c * 4 + 3] = q.w * m.w;
                }
            } else {
                const float* src2 = Bp + (size_t)(k0 + kk2) * ldn + n0 + ngrp;
#pragma unroll
                for (int c = 0; c < 4; c++) {
                    float4 v = *(const float4*)(src2 + c * 4);
                    aB[c * 4 + 0] = v.x; aB[c * 4 + 1] = v.y; aB[c * 4 + 2] = v.z; aB[c * 4 + 3] = v.w;
                }
            }
        }

        // ---- compute chunk i from stage s ----
#pragma unroll
        for (int kk = 0; kk < 32; kk += 16) {
            uint32_t af[2][4];
#pragma unroll
            for (int mi = 0; mi < 2; mi++) {
                int base = (wm + mi * 16 + g) * KS + kk + 2 * tg;
                af[mi][0] = *(const uint32_t*)&As[s][base];
                af[mi][1] = *(const uint32_t*)&As[s][base + 8 * KS];
                af[mi][2] = *(const uint32_t*)&As[s][base + 8];
                af[mi][3] = *(const uint32_t*)&As[s][base + 8 * KS + 8];
            }
            uint32_t bf[8][2];
#pragma unroll
            for (int ni = 0; ni < 8; ni++) {
                int base = (wn + ni * 8 + g) * KS + kk + 2 * tg;
                bf[ni][0] = *(const uint32_t*)&Bs[s][base];
                bf[ni][1] = *(const uint32_t*)&Bs[s][base + 8];
            }
#pragma unroll
            for (int mi = 0; mi < 2; mi++)
#pragma unroll
                for (int ni = 0; ni < 8; ni++)
                    mma_f16(acc[mi][ni], af[mi], bf[ni]);
        }
        __syncthreads();
    }

    // ---- epilogue ----
#pragma unroll
    for (int mi = 0; mi < 2; mi++) {
        int r0 = m0 + wm + mi * 16 + g;
#pragma unroll
        for (int ni = 0; ni < 8; ni++) {
            int cg = n0 + wn + ni * 8 + 2 * tg;
#pragma unroll
            for (int hh = 0; hh < 2; hh++) {
                int mg = r0 + hh * 8;
#pragma unroll
                for (int jj = 0; jj < 2; jj++) {
                    int ng = cg + jj;
                    float v = acc[mi][ni][hh * 2 + jj];
                    if (EPI == 0) v = (v >= 0.0f) ? v : 0.1f * v;
                    if (EPI == 2 || EPI == 3 || EPI == 4) v += __ldg(bias + ng);
                    if (EPI == 3) v = tanhf(v);
                    if (EPI == 4) {
                        size_t idx = (size_t)mg * ldc + ng;
                        float nv = tanhf(v) + extra[idx];
                        nv = fminf(1.0f, fmaxf(-1.0f, nv));
                        extra[idx] = nv;
                    } else {
                        C[(size_t)mg * ldc + ng] = v;
                    }
                }
            }
        }
    }
}

// ---------------- init: matrix = 1, smooth = 10 ----------------
__global__ void init_kernel(float* __restrict__ matrix, float* __restrict__ smooth) {
    size_t i = (size_t)blockIdx.x * blockDim.x + threadIdx.x;
    if (i < (size_t)Bb * NQ * D) matrix[i] = 1.0f;
    if (i < (size_t)Bb * NQ) smooth[i] = 10.0f;
}

// ---------------- row L2 norm (over q) of S ----------------
__global__ void rownorm_kernel(const float* __restrict__ S, float* __restrict__ invn) {
    int bc = blockIdx.x;
    float v = S[(size_t)bc * NQ + threadIdx.x];
    float s = warp_sum(v * v);
    __shared__ float red[8];
    if ((threadIdx.x & 31) == 0) red[threadIdx.x >> 5] = s;
    __syncthreads();
    if (threadIdx.x == 0) {
        float t = red[0] + red[1] + red[2] + red[3] + red[4] + red[5] + red[6] + red[7];
        invn[bc] = 1.0f / (sqrtf(t) + 1e-8f);
    }
}

// ---------------- softmax over c with per-(b,q) smooth; transposes S -> attn ----------------
__global__ void __launch_bounds__(256) softmax_kernel(
    const float* __restrict__ S, const float* __restrict__ invn,
    const float* __restrict__ smooth, float* __restrict__ attn)
{
    int b = blockIdx.y;
    int q0 = blockIdx.x * 32;
    __shared__ float sm[NC][33];
    const float* Sb = S + (size_t)b * NC * NQ;
    for (int idx = threadIdx.x; idx < NC * 32; idx += 256) {
        int c = idx >> 5, qq = idx & 31;
        sm[c][qq] = Sb[(size_t)c * NQ + q0 + qq] * invn[b * NC + c];
    }
    __syncthreads();
    int warp = threadIdx.x >> 5, lane = threadIdx.x & 31;
    for (int qi = warp; qi < 32; qi += 8) {
        float sf = smooth[b * NQ + q0 + qi];
        float v0 = sm[lane][qi] * sf;
        float v1 = sm[lane + 32][qi] * sf;
        float v2 = sm[lane + 64][qi] * sf;
        float v3 = sm[lane + 96][qi] * sf;
        float mx = fmaxf(fmaxf(v0, v1), fmaxf(v2, v3));
#pragma unroll
        for (int o = 16; o > 0; o >>= 1) mx = fmaxf(mx, __shfl_xor_sync(0xffffffffu, mx, o));
        float e0 = expf(v0 - mx), e1 = expf(v1 - mx), e2 = expf(v2 - mx), e3 = expf(v3 - mx);
        float s = warp_sum(e0 + e1 + e2 + e3);
        float inv = 1.0f / s;
        float* ap = attn + ((size_t)b * NQ + q0 + qi) * NC;
        ap[lane] = e0 * inv; ap[lane + 32] = e1 * inv;
        ap[lane + 64] = e2 * inv; ap[lane + 96] = e3 * inv;
    }
}

// ---------------- in-place L2 norm over last dim (256) ----------------
__global__ void l2norm256_kernel(float* __restrict__ X) {
    float* p = X + (size_t)blockIdx.x * AD;
    float v = p[threadIdx.x];
    float s = warp_sum(v * v);
    __shared__ float red[8];
    if ((threadIdx.x & 31) == 0) red[threadIdx.x >> 5] = s;
    __syncthreads();
    float t = red[0] + red[1] + red[2] + red[3] + red[4] + red[5] + red[6] + red[7];
    p[threadIdx.x] = v / (sqrtf(t) + 1e-8f);
}

// ---------------- smooth update: smooth = relu(sh . w2 + b2 + smooth) ----------------
__global__ void sw_reduce_kernel(const float* __restrict__ sh, const float* __restrict__ w2,
                                 const float* __restrict__ b2, float* __restrict__ smooth)
{
    int row = blockIdx.x * 8 + (threadIdx.x >> 5);
    int lane = threadIdx.x & 31;
    const float* r = sh + (size_t)row * HD;
    float s = r[lane] * w2[lane] + r[lane + 32] * w2[lane + 32]
            + r[lane + 64] * w2[lane + 64] + r[lane + 96] * w2[lane + 96];
    s = warp_sum(s);
    if (lane == 0) smooth[row] = fmaxf(0.0f, s + b2[0] + smooth[row]);
}

// ---------------- orchestration ----------------
extern "C" void kernel_launch(void* const* d_in, const int* in_sizes, int n_in,
                              void* d_out, int out_size)
{
    const float* query = (const float*)d_in[0];
    const float* ctx   = (const float*)d_in[1];
    const float* cw_W  = (const float*)d_in[2];
    const float* cw_b  = (const float*)d_in[3];
    const float* sw_W1 = (const float*)d_in[4];
    const float* sw_b1 = (const float*)d_in[5];
    const float* sw_W2 = (const float*)d_in[6];
    const float* sw_b2 = (const float*)d_in[7];
    const float* mw_W1 = (const float*)d_in[8];
    const float* mw_b1 = (const float*)d_in[9];
    const float* mw_W2 = (const float*)d_in[10];
    const float* mw_b2 = (const float*)d_in[11];

    float* out      = (float*)d_out;
    float* out_q    = out;
    float* out_wc   = out + (size_t)Bb * NQ * D;
    float* out_attn = out + 2 * (size_t)Bb * NQ * D;

    float *pS, *pinvn, *pattn, *pwc, *pmat, *psm, *pcom, *ph1, *psh;
    cudaGetSymbolAddress((void**)&pS,    g_S);
    cudaGetSymbolAddress((void**)&pinvn, g_invn);
    cudaGetSymbolAddress((void**)&pattn, g_attn);
    cudaGetSymbolAddress((void**)&pwc,   g_wc);
    cudaGetSymbolAddress((void**)&pmat,  g_matrix);
    cudaGetSymbolAddress((void**)&psm,   g_smooth);
    cudaGetSymbolAddress((void**)&pcom,  g_common);
    cudaGetSymbolAddress((void**)&ph1,   g_h1);
    cudaGetSymbolAddress((void**)&psh,   g_sh);

    init_kernel<<<(Bb * NQ * D + 255) / 256, 256>>>(pmat, psm);

    for (int i = 0; i < 2; i++) {
        // ---- attention scan ----
        // S[b] = leaky( ctx[b] @ (query*matrix)[b]^T ): M=NC, N=NQ(2 tiles), K=D
        hgemm<0,1,0><<<dim3(2, 1, Bb), 256>>>(
            ctx, nullptr, query, pmat, nullptr, pS, nullptr,
            D, 0, NQ, (size_t)NC * D, (size_t)NQ * D, (size_t)NC * NQ);
        rownorm_kernel<<<Bb * NC, 256>>>(pS, pinvn);
        softmax_kernel<<<dim3(8, Bb), 256>>>(pS, pinvn, psm, pattn);
        // wc[b] = attn[b] @ ctx[b]: M=NQ(2), N=D(8), K=NC
        hgemm<0,2,1><<<dim3(8, 2, Bb), 256>>>(
            pattn, nullptr, ctx, nullptr, nullptr, pwc, nullptr,
            NC, D, D, (size_t)NQ * NC, (size_t)NC * D, (size_t)NQ * D);

        // ---- common = l2norm((q - wc)^2 @ cw_W + cw_b) ----
        hgemm<1,2,2><<<dim3(2, 256, 1), 256>>>(
            query, pwc, cw_W + (size_t)i * D * AD, nullptr, cw_b + (size_t)i * AD,
            pcom, nullptr, D, AD, AD, 0, 0, 0);
        l2norm256_kernel<<<Bb * NQ, 256>>>(pcom);

        // ---- smooth branch ----
        hgemm<0,2,3><<<dim3(1, 256, 1), 256>>>(
            pcom, nullptr, sw_W1 + (size_t)i * AD * HD, nullptr, sw_b1 + (size_t)i * HD,
            psh, nullptr, AD, HD, HD, 0, 0, 0);
        sw_reduce_kernel<<<Bb * NQ / 8, 256>>>(psh, sw_W2 + (size_t)i * HD, sw_b2 + i, psm);

        // ---- matrix branch ----
        hgemm<0,2,3><<<dim3(4, 256, 1), 256>>>(
            pcom, nullptr, mw_W1 + (size_t)i * AD * MD, nullptr, mw_b1 + (size_t)i * MD,
            ph1, nullptr, AD, MD, MD, 0, 0, 0);
        hgemm<0,2,4><<<dim3(8, 256, 1), 256>>>(
            ph1, nullptr, mw_W2 + (size_t)i * MD * D, nullptr, mw_b2 + (size_t)i * D,
            nullptr, pmat, MD, D, D, 0, 0, 0);
    }

    // ---- final attention scan into d_out ----
    hgemm<0,1,0><<<dim3(2, 1, Bb), 256>>>(
        ctx, nullptr, query, pmat, nullptr, pS, nullptr,
        D, 0, NQ, (size_t)NC * D, (size_t)NQ * D, (size_t)NC * NQ);
    rownorm_kernel<<<Bb * NC, 256>>>(pS, pinvn);
    softmax_kernel<<<dim3(8, Bb), 256>>>(pS, pinvn, psm, out_attn);
    hgemm<0,2,1><<<dim3(8, 2, Bb), 256>>>(
        out_attn, nullptr, ctx, nullptr, nullptr, out_wc, nullptr,
        NC, D, D, (size_t)NQ * NC, (size_t)NC * D, (size_t)NQ * D);

    cudaMemcpyAsync(out_q, query, (size_t)Bb * NQ * D * sizeof(float),
                    cudaMemcpyDeviceToDevice, 0);
}

// round 5
// speedup vs baseline: 1.3966x; 1.3966x over previous
#include <cuda_runtime.h>
#include <cuda_fp16.h>
#include <stdint.h>
#include <math.h>

// Problem constants
#define Bb 128
#define NQ 256
#define NC 128
#define D  1024
#define AD 256
#define HD 128
#define MD 512

// weight pack offsets (halves)
#define W_CW  0
#define W_SW1 (W_CW  + 2 * D * AD)
#define W_MW1 (W_SW1 + 2 * AD * HD)
#define W_MW2 (W_MW1 + 2 * AD * MD)
#define W_TOT (W_MW2 + 2 * MD * D)

// ---------------- scratch (device globals) ----------------
__device__ float  g_S[Bb * NC * NQ];
__device__ float  g_invn[Bb * NC];
__device__ float  g_matrix[Bb * NQ * D];
__device__ float  g_smooth[Bb * NQ];
__device__ float  g_common[Bb * NQ * AD];
__device__ __half g_qm16[Bb * NQ * D];
__device__ __half g_ctx16[Bb * NC * D];
__device__ __half g_attn16[Bb * NQ * NC];
__device__ __half g_d16[Bb * NQ * D];
__device__ __half g_com16[Bb * NQ * AD];
__device__ __half g_h16[Bb * NQ * MD];
__device__ __half g_sh16[Bb * NQ * HD];
__device__ __half g_w16[W_TOT];

// ---------------- utils ----------------
__device__ __forceinline__ float warp_sum(float v) {
#pragma unroll
    for (int o = 16; o > 0; o >>= 1) v += __shfl_xor_sync(0xffffffffu, v, o);
    return v;
}

__device__ __forceinline__ uint32_t smem_u32(const void* p) {
    uint32_t a;
    asm("{ .reg .u64 t; cvta.to.shared.u64 t, %1; cvt.u32.u64 %0, t; }" : "=r"(a) : "l"(p));
    return a;
}

__device__ __forceinline__ void cpa16(uint32_t dst, const void* src) {
    asm volatile("cp.async.cg.shared.global [%0], [%1], 16;" :: "r"(dst), "l"(src));
}
#define CPA_COMMIT() asm volatile("cp.async.commit_group;" ::: "memory")
#define CPA_WAIT1()  asm volatile("cp.async.wait_group 1;" ::: "memory")

__device__ __forceinline__ void ldm4(uint32_t* r, uint32_t a) {
    asm volatile("ldmatrix.sync.aligned.m8n8.x4.shared.b16 {%0,%1,%2,%3}, [%4];"
        : "=r"(r[0]), "=r"(r[1]), "=r"(r[2]), "=r"(r[3]) : "r"(a));
}
__device__ __forceinline__ void ldm4t(uint32_t* r, uint32_t a) {
    asm volatile("ldmatrix.sync.aligned.m8n8.x4.trans.shared.b16 {%0,%1,%2,%3}, [%4];"
        : "=r"(r[0]), "=r"(r[1]), "=r"(r[2]), "=r"(r[3]) : "r"(a));
}

__device__ __forceinline__ void mma16(float* c, const uint32_t* a, const uint32_t* b) {
    asm volatile(
        "mma.sync.aligned.m16n8k16.row.col.f32.f16.f16.f32 "
        "{%0,%1,%2,%3},{%4,%5,%6,%7},{%8,%9},{%0,%1,%2,%3};"
        : "+f"(c[0]), "+f"(c[1]), "+f"(c[2]), "+f"(c[3])
        : "r"(a[0]), "r"(a[1]), "r"(a[2]), "r"(a[3]), "r"(b[0]), "r"(b[1]));
}

#define STAGE_BYTES 32768
#define SMEM_BYTES  (3 * STAGE_BYTES)

// ---------------- pipelined fp16 GEMM (cp.async + ldmatrix) ----------------
// Tile 128(M) x 128(N), K chunks of 64 halves (128B rows), 3-stage cp.async ring.
// BL: 0 -> B stored [n][k];  1 -> B stored [k][n] (row stride ldn)
// EPI: 0 leaky->f32 | 1 (q-v)^2->half | 2 plain f32 | 3 +bias f32
//      4 tanh(v+bias)->half | 5 matrix update + qm16
template<int BL, int EPI>
__global__ void __launch_bounds__(256, 1) hgemm(
    const __half* __restrict__ A, const __half* __restrict__ Bw,
    const float* __restrict__ bias, void* __restrict__ Cout,
    const float* __restrict__ qsrc, float* __restrict__ mat,
    __half* __restrict__ qm16,
    int K, int ldn, int ldc, size_t sA, size_t sB, size_t sC)
{
    extern __shared__ __half smemh[];
    const uint32_t sbase = smem_u32(smemh);

    const int tid = threadIdx.x;
    const int lane = tid & 31, warp = tid >> 5;
    const int wm = (warp & 3) * 32, wn = (warp >> 2) * 64;
    const int z = blockIdx.z;
    const int m0 = blockIdx.y * 128, n0 = blockIdx.x * 128;

    const __half* Ab = A + (size_t)z * sA;
    const __half* Bp = Bw + (size_t)z * sB;

    const int ar  = tid & 127, acb = (tid >> 7) * 4;   // A / BL0 loader
    const int bkr = tid & 63,  bcb = (tid >> 6) * 4;   // BL1 loader
    const int NCH = K >> 6;

    float acc[2][8][4];
#pragma unroll
    for (int i = 0; i < 2; i++)
#pragma unroll
        for (int j = 0; j < 8; j++)
#pragma unroll
            for (int r = 0; r < 4; r++) acc[i][j][r] = 0.0f;

    auto load_chunk = [&](int stage, int ch) {
        const uint32_t Abase = sbase + stage * STAGE_BYTES;
        const uint32_t Bbase = Abase + 16384;
        const __half* ga = Ab + (size_t)(m0 + ar) * K + ch * 64 + acb * 8;
#pragma unroll
        for (int j = 0; j < 4; j++) {
            int c = acb + j;
            cpa16(Abase + ar * 128 + (((uint32_t)(c ^ (ar & 7))) << 4), ga + j * 8);
        }
        if (BL == 0) {
            const __half* gb = Bp + (size_t)(n0 + ar) * K + ch * 64 + acb * 8;
#pragma unroll
            for (int j = 0; j < 4; j++) {
                int c = acb + j;
                cpa16(Bbase + ar * 128 + (((uint32_t)(c ^ (ar & 7))) << 4), gb + j * 8);
            }
        } else {
            const __half* gb = Bp + (size_t)(ch * 64 + bkr) * ldn + n0 + bcb * 8;
#pragma unroll
            for (int j = 0; j < 4; j++) {
                int c = bcb + j;
                cpa16(Bbase + bkr * 256 + (((uint32_t)(c ^ (bkr & 15))) << 4), gb + j * 8);
            }
        }
    };

    auto compute = [&](int stage) {
        const uint32_t Abase = sbase + stage * STAGE_BYTES;
        const uint32_t Bbase = Abase + 16384;
#pragma unroll
        for (int s16 = 0; s16 < 4; s16++) {
            uint32_t a[2][4];
#pragma unroll
            for (int mi = 0; mi < 2; mi++) {
                int row = wm + mi * 16 + (lane & 15);
                int c = s16 * 2 + (lane >> 4);
                ldm4(a[mi], Abase + row * 128 + (((uint32_t)(c ^ (row & 7))) << 4));
            }
            uint32_t bf[4][4];
#pragma unroll
            for (int nb = 0; nb < 4; nb++) {
                if (BL == 0) {
                    int row = wn + nb * 16 + (lane & 15);
                    int c = s16 * 2 + (lane >> 4);
                    ldm4(bf[nb], Bbase + row * 128 + (((uint32_t)(c ^ (row & 7))) << 4));
                } else {
                    int kr = s16 * 16 + ((lane >> 4) << 3) + (lane & 7);
                    int c = ((wn + nb * 16) >> 3) + ((lane >> 3) & 1);
                    ldm4t(bf[nb], Bbase + kr * 256 + (((uint32_t)(c ^ (kr & 15))) << 4));
                }
            }
#pragma unroll
            for (int mi = 0; mi < 2; mi++)
#pragma unroll
                for (int nb = 0; nb < 4; nb++) {
                    uint32_t b0[2] = {bf[nb][0], bf[nb][2]};
                    uint32_t b1[2] = {bf[nb][1], bf[nb][3]};
                    mma16(acc[mi][2 * nb], a[mi], b0);
                    mma16(acc[mi][2 * nb + 1], a[mi], b1);
                }
        }
    };

    // prologue: 2 chunks in flight
    for (int p = 0; p < 2; p++) {
        if (p < NCH) load_chunk(p, p);
        CPA_COMMIT();
    }
    for (int i = 0; i < NCH; i++) {
        CPA_WAIT1();
        __syncthreads();
        if (i + 2 < NCH) load_chunk((i + 2) % 3, i + 2);
        CPA_COMMIT();
        compute(i % 3);
    }

    // ---------------- epilogue ----------------
    const int g = lane >> 2, tg = lane & 3;
#pragma unroll
    for (int mi = 0; mi < 2; mi++) {
#pragma unroll
        for (int ni = 0; ni < 8; ni++) {
            int n = n0 + wn + ni * 8 + 2 * tg;
#pragma unroll
            for (int hh = 0; hh < 2; hh++) {
                int m = m0 + wm + mi * 16 + g + hh * 8;
                size_t off = (size_t)z * sC + (size_t)m * ldc + n;
#pragma unroll
                for (int jj = 0; jj < 2; jj++) {
                    float v = acc[mi][ni][hh * 2 + jj];
                    size_t o = off + jj;
                    int nn = n + jj;
                    if (EPI == 0) {
                        ((float*)Cout)[o] = (v >= 0.0f) ? v : 0.1f * v;
                    } else if (EPI == 1) {
                        float t = qsrc[o] - v;
                        ((__half*)Cout)[o] = __float2half_rn(t * t);
                    } else if (EPI == 2) {
                        ((float*)Cout)[o] = v;
                    } else if (EPI == 3) {
                        ((float*)Cout)[o] = v + __ldg(bias + nn);
                    } else if (EPI == 4) {
                        ((__half*)Cout)[o] = __float2half_rn(tanhf(v + __ldg(bias + nn)));
                    } else {
                        float t = tanhf(v + __ldg(bias + nn));
                        float nm = fminf(1.0f, fmaxf(-1.0f, t + mat[o]));
                        mat[o] = nm;
                        qm16[o] = __float2half_rn(qsrc[o] * nm);
                    }
                }
            }
        }
    }
}

// ---------------- elementwise kernels ----------------
__global__ void init_kernel(const float* __restrict__ query,
                            float* __restrict__ matrix, float* __restrict__ smooth,
                            __half* __restrict__ qm16) {
    size_t i = (size_t)blockIdx.x * blockDim.x + threadIdx.x;
    if (i < (size_t)Bb * NQ * D) {
        matrix[i] = 1.0f;
        qm16[i] = __float2half_rn(query[i]);
    }
    if (i < (size_t)Bb * NQ) smooth[i] = 10.0f;
}

__global__ void convert_kernel(const float* __restrict__ src, __half* __restrict__ dst, int n) {
    int i = blockIdx.x * blockDim.x + threadIdx.x;
    if (i < n) dst[i] = __float2half_rn(src[i]);
}

__global__ void rownorm_kernel(const float* __restrict__ S, float* __restrict__ invn) {
    int bc = blockIdx.x;
    float v = S[(size_t)bc * NQ + threadIdx.x];
    float s = warp_sum(v * v);
    __shared__ float red[8];
    if ((threadIdx.x & 31) == 0) red[threadIdx.x >> 5] = s;
    __syncthreads();
    if (threadIdx.x == 0) {
        float t = red[0] + red[1] + red[2] + red[3] + red[4] + red[5] + red[6] + red[7];
        invn[bc] = 1.0f / (sqrtf(t) + 1e-8f);
    }
}

__global__ void __launch_bounds__(256) softmax_kernel(
    const float* __restrict__ S, const float* __restrict__ invn,
    const float* __restrict__ smooth, __half* __restrict__ a16,
    float* __restrict__ a32)
{
    int b = blockIdx.y;
    int q0 = blockIdx.x * 32;
    __shared__ float sm[NC][33];
    const float* Sb = S + (size_t)b * NC * NQ;
    for (int idx = threadIdx.x; idx < NC * 32; idx += 256) {
        int c = idx >> 5, qq = idx & 31;
        sm[c][qq] = Sb[(size_t)c * NQ + q0 + qq] * invn[b * NC + c];
    }
    __syncthreads();
    int warp = threadIdx.x >> 5, lane = threadIdx.x & 31;
    for (int qi = warp; qi < 32; qi += 8) {
        float sf = smooth[b * NQ + q0 + qi];
        float v0 = sm[lane][qi] * sf;
        float v1 = sm[lane + 32][qi] * sf;
        float v2 = sm[lane + 64][qi] * sf;
        float v3 = sm[lane + 96][qi] * sf;
        float mx = fmaxf(fmaxf(v0, v1), fmaxf(v2, v3));
#pragma unroll
        for (int o = 16; o > 0; o >>= 1) mx = fmaxf(mx, __shfl_xor_sync(0xffffffffu, mx, o));
        float e0 = expf(v0 - mx), e1 = expf(v1 - mx), e2 = expf(v2 - mx), e3 = expf(v3 - mx);
        float s = warp_sum(e0 + e1 + e2 + e3);
        float inv = 1.0f / s;
        size_t base = ((size_t)b * NQ + q0 + qi) * NC;
        a16[base + lane]      = __float2half_rn(e0 * inv);
        a16[base + lane + 32] = __float2half_rn(e1 * inv);
        a16[base + lane + 64] = __float2half_rn(e2 * inv);
        a16[base + lane + 96] = __float2half_rn(e3 * inv);
        if (a32) {
            a32[base + lane]      = e0 * inv;
            a32[base + lane + 32] = e1 * inv;
            a32[base + lane + 64] = e2 * inv;
            a32[base + lane + 96] = e3 * inv;
        }
    }
}

__global__ void l2norm256_kernel(const float* __restrict__ X, __half* __restrict__ Y) {
    const float* p = X + (size_t)blockIdx.x * AD;
    float v = p[threadIdx.x];
    float s = warp_sum(v * v);
    __shared__ float red[8];
    if ((threadIdx.x & 31) == 0) red[threadIdx.x >> 5] = s;
    __syncthreads();
    float t = red[0] + red[1] + red[2] + red[3] + red[4] + red[5] + red[6] + red[7];
    Y[(size_t)blockIdx.x * AD + threadIdx.x] = __float2half_rn(v / (sqrtf(t) + 1e-8f));
}

__global__ void sw_reduce_kernel(const __half* __restrict__ sh, const float* __restrict__ w2,
                                 const float* __restrict__ b2, float* __restrict__ smooth)
{
    int row = blockIdx.x * 8 + (threadIdx.x >> 5);
    int lane = threadIdx.x & 31;
    const __half* r = sh + (size_t)row * HD;
    float s = __half2float(r[lane]) * w2[lane]
            + __half2float(r[lane + 32]) * w2[lane + 32]
            + __half2float(r[lane + 64]) * w2[lane + 64]
            + __half2float(r[lane + 96]) * w2[lane + 96];
    s = warp_sum(s);
    if (lane == 0) smooth[row] = fmaxf(0.0f, s + b2[0] + smooth[row]);
}

// ---------------- orchestration ----------------
extern "C" void kernel_launch(void* const* d_in, const int* in_sizes, int n_in,
                              void* d_out, int out_size)
{
    const float* query = (const float*)d_in[0];
    const float* ctx   = (const float*)d_in[1];
    const float* cw_W  = (const float*)d_in[2];
    const float* cw_b  = (const float*)d_in[3];
    const float* sw_W1 = (const float*)d_in[4];
    const float* sw_b1 = (const float*)d_in[5];
    const float* sw_W2 = (const float*)d_in[6];
    const float* sw_b2 = (const float*)d_in[7];
    const float* mw_W1 = (const float*)d_in[8];
    const float* mw_b1 = (const float*)d_in[9];
    const float* mw_W2 = (const float*)d_in[10];
    const float* mw_b2 = (const float*)d_in[11];

    float* out      = (float*)d_out;
    float* out_q    = out;
    float* out_wc   = out + (size_t)Bb * NQ * D;
    float* out_attn = out + 2 * (size_t)Bb * NQ * D;

    float *pS, *pinvn, *pmat, *psm, *pcom;
    __half *pqm, *pctx16, *pattn16, *pd16, *pcom16, *ph16, *psh16, *pw16;
    cudaGetSymbolAddress((void**)&pS,      g_S);
    cudaGetSymbolAddress((void**)&pinvn,   g_invn);
    cudaGetSymbolAddress((void**)&pmat,    g_matrix);
    cudaGetSymbolAddress((void**)&psm,     g_smooth);
    cudaGetSymbolAddress((void**)&pcom,    g_common);
    cudaGetSymbolAddress((void**)&pqm,     g_qm16);
    cudaGetSymbolAddress((void**)&pctx16,  g_ctx16);
    cudaGetSymbolAddress((void**)&pattn16, g_attn16);
    cudaGetSymbolAddress((void**)&pd16,    g_d16);
    cudaGetSymbolAddress((void**)&pcom16,  g_com16);
    cudaGetSymbolAddress((void**)&ph16,    g_h16);
    cudaGetSymbolAddress((void**)&psh16,   g_sh16);
    cudaGetSymbolAddress((void**)&pw16,    g_w16);

    cudaFuncSetAttribute(hgemm<0,0>, cudaFuncAttributeMaxDynamicSharedMemorySize, SMEM_BYTES);
    cudaFuncSetAttribute(hgemm<1,1>, cudaFuncAttributeMaxDynamicSharedMemorySize, SMEM_BYTES);
    cudaFuncSetAttribute(hgemm<1,2>, cudaFuncAttributeMaxDynamicSharedMemorySize, SMEM_BYTES);
    cudaFuncSetAttribute(hgemm<1,3>, cudaFuncAttributeMaxDynamicSharedMemorySize, SMEM_BYTES);
    cudaFuncSetAttribute(hgemm<1,4>, cudaFuncAttributeMaxDynamicSharedMemorySize, SMEM_BYTES);
    cudaFuncSetAttribute(hgemm<1,5>, cudaFuncAttributeMaxDynamicSharedMemorySize, SMEM_BYTES);

    // init + conversions
    init_kernel<<<(Bb * NQ * D + 255) / 256, 256>>>(query, pmat, psm, pqm);
    convert_kernel<<<(Bb * NC * D + 255) / 256, 256>>>(ctx, pctx16, Bb * NC * D);
    convert_kernel<<<(2 * D * AD + 255) / 256, 256>>>(cw_W,  pw16 + W_CW,  2 * D * AD);
    convert_kernel<<<(2 * AD * HD + 255) / 256, 256>>>(sw_W1, pw16 + W_SW1, 2 * AD * HD);
    convert_kernel<<<(2 * AD * MD + 255) / 256, 256>>>(mw_W1, pw16 + W_MW1, 2 * AD * MD);
    convert_kernel<<<(2 * MD * D + 255) / 256, 256>>>(mw_W2, pw16 + W_MW2, 2 * MD * D);

    for (int i = 0; i < 2; i++) {
        // S = leaky(ctx @ qm^T)
        hgemm<0,0><<<dim3(2, 1, Bb), 256, SMEM_BYTES>>>(
            pctx16, pqm, nullptr, pS, nullptr, nullptr, nullptr,
            D, 0, NQ, (size_t)NC * D, (size_t)NQ * D, (size_t)NC * NQ);
        rownorm_kernel<<<Bb * NC, 256>>>(pS, pinvn);
        softmax_kernel<<<dim3(8, Bb), 256>>>(pS, pinvn, psm, pattn16, nullptr);
        // d16 = (q - attn@ctx)^2
        hgemm<1,1><<<dim3(8, 2, Bb), 256, SMEM_BYTES>>>(
            pattn16, pctx16, nullptr, pd16, query, nullptr, nullptr,
            NC, D, D, (size_t)NQ * NC, (size_t)NC * D, (size_t)NQ * D);
        // common = d16 @ cw_W + b
        hgemm<1,3><<<dim3(2, 256, 1), 256, SMEM_BYTES>>>(
            pd16, pw16 + W_CW + (size_t)i * D * AD, cw_b + (size_t)i * AD, pcom,
            nullptr, nullptr, nullptr, D, AD, AD, 0, 0, 0);
        l2norm256_kernel<<<Bb * NQ, 256>>>(pcom, pcom16);
        // smooth branch
        hgemm<1,4><<<dim3(1, 256, 1), 256, SMEM_BYTES>>>(
            pcom16, pw16 + W_SW1 + (size_t)i * AD * HD, sw_b1 + (size_t)i * HD, psh16,
            nullptr, nullptr, nullptr, AD, HD, HD, 0, 0, 0);
        sw_reduce_kernel<<<Bb * NQ / 8, 256>>>(psh16, sw_W2 + (size_t)i * HD, sw_b2 + i, psm);
        // matrix branch
        hgemm<1,4><<<dim3(4, 256, 1), 256, SMEM_BYTES>>>(
            pcom16, pw16 + W_MW1 + (size_t)i * AD * MD, mw_b1 + (size_t)i * MD, ph16,
            nullptr, nullptr, nullptr, AD, MD, MD, 0, 0, 0);
        hgemm<1,5><<<dim3(8, 256, 1), 256, SMEM_BYTES>>>(
            ph16, pw16 + W_MW2 + (size_t)i * MD * D, mw_b2 + (size_t)i * D, nullptr,
            query, pmat, pqm, MD, D, D, 0, 0, 0);
    }

    // final scan -> d_out
    hgemm<0,0><<<dim3(2, 1, Bb), 256, SMEM_BYTES>>>(
        pctx16, pqm, nullptr, pS, nullptr, nullptr, nullptr,
        D, 0, NQ, (size_t)NC * D, (size_t)NQ * D, (size_t)NC * NQ);
    rownorm_kernel<<<Bb * NC, 256>>>(pS, pinvn);
    softmax_kernel<<<dim3(8, Bb), 256>>>(pS, pinvn, psm, pattn16, out_attn);
    hgemm<1,2><<<dim3(8, 2, Bb), 256, SMEM_BYTES>>>(
        pattn16, pctx16, nullptr, out_wc, nullptr, nullptr, nullptr,
        NC, D, D, (size_t)NQ * NC, (size_t)NC * D, (size_t)NQ * D);

    cudaMemcpyAsync(out_q, query, (size_t)Bb * NQ * D * sizeof(float),
                    cudaMemcpyDeviceToDevice, 0);
}

// round 7
// speedup vs baseline: 1.6194x; 1.1595x over previous
#include <cuda_runtime.h>
#include <cuda_fp16.h>
#include <stdint.h>
#include <math.h>

// Problem constants
#define Bb 128
#define NQ 256
#define NC 128
#define D  1024
#define AD 256
#define HD 128
#define MD 512

// transposed weight pack offsets (halves)
#define W_CW  0
#define W_SW1 (W_CW  + 2 * D * AD)
#define W_MW1 (W_SW1 + 2 * AD * HD)
#define W_MW2 (W_MW1 + 2 * AD * MD)
#define W_TOT (W_MW2 + 2 * MD * D)

// ---------------- scratch (device globals) ----------------
__device__ float  g_S[Bb * NC * NQ];
__device__ float  g_invn[Bb * NC];
__device__ float  g_matrix[Bb * NQ * D];
__device__ float  g_smooth[Bb * NQ];
__device__ float  g_common[Bb * NQ * AD];
__device__ __half g_qm16[Bb * NQ * D];
__device__ __half g_ctx16[Bb * NC * D];    // [b][c][d]
__device__ __half g_ctxT16[Bb * D * NC];   // [b][d][c]
__device__ __half g_attn16[Bb * NQ * NC];
__device__ __half g_d16[Bb * NQ * D];
__device__ __half g_com16[Bb * NQ * AD];
__device__ __half g_h16[Bb * NQ * MD];
__device__ __half g_sh16[Bb * NQ * HD];
__device__ __half g_w16[W_TOT];            // all weights transposed to [n][k]

// ---------------- utils ----------------
__device__ __forceinline__ float warp_sum(float v) {
#pragma unroll
    for (int o = 16; o > 0; o >>= 1) v += __shfl_xor_sync(0xffffffffu, v, o);
    return v;
}

__device__ __forceinline__ uint32_t smem_u32(const void* p) {
    uint32_t a;
    asm("{ .reg .u64 t; cvta.to.shared.u64 t, %1; cvt.u32.u64 %0, t; }" : "=r"(a) : "l"(p));
    return a;
}

__device__ __forceinline__ void cpa16(uint32_t dst, const void* src) {
    asm volatile("cp.async.cg.shared.global [%0], [%1], 16;" :: "r"(dst), "l"(src));
}
#define CPA_COMMIT() asm volatile("cp.async.commit_group;" ::: "memory")
#define CPA_WAIT1()  asm volatile("cp.async.wait_group 1;" ::: "memory")
#define CPA_WAIT0()  asm volatile("cp.async.wait_group 0;" ::: "memory")

__device__ __forceinline__ void ldm4(uint32_t* r, uint32_t a) {
    asm volatile("ldmatrix.sync.aligned.m8n8.x4.shared.b16 {%0,%1,%2,%3}, [%4];"
        : "=r"(r[0]), "=r"(r[1]), "=r"(r[2]), "=r"(r[3]) : "r"(a));
}

__device__ __forceinline__ void mma16(float* c, const uint32_t* a, const uint32_t* b) {
    asm volatile(
        "mma.sync.aligned.m16n8k16.row.col.f32.f16.f16.f32 "
        "{%0,%1,%2,%3},{%4,%5,%6,%7},{%8,%9},{%0,%1,%2,%3};"
        : "+f"(c[0]), "+f"(c[1]), "+f"(c[2]), "+f"(c[3])
        : "r"(a[0]), "r"(a[1]), "r"(a[2]), "r"(a[3]), "r"(b[0]), "r"(b[1]));
}

#define STAGE_BYTES 32768
#define SMEM_BYTES  (2 * STAGE_BYTES)

// ---------------- pipelined fp16 GEMM (cp.async + ldmatrix, all [n][k] B) -------
// Tile 128(M) x 128(N), K chunks of 64 halves (128B rows), 2-stage ring, 2 CTA/SM.
// EPI: 0 leaky->f32 | 1 (q-v)^2->half | 2 plain f32 | 3 +bias f32
//      4 tanh(v+bias)->half | 5 matrix update + qm16
template<int EPI>
__global__ void __launch_bounds__(256, 2) hgemm(
    const __half* __restrict__ A, const __half* __restrict__ Bw,
    const float* __restrict__ bias, void* __restrict__ Cout,
    const float* __restrict__ qsrc, float* __restrict__ mat,
    __half* __restrict__ qm16,
    int K, int ldc, size_t sA, size_t sB, size_t sC)
{
    extern __shared__ __half smemh[];
    const uint32_t sbase = smem_u32(smemh);

    const int tid = threadIdx.x;
    const int lane = tid & 31, warp = tid >> 5;
    const int wm = (warp & 3) * 32, wn = (warp >> 2) * 64;
    const int z = blockIdx.z;
    const int m0 = blockIdx.y * 128, n0 = blockIdx.x * 128;

    const __half* Ab = A + (size_t)z * sA;
    const __half* Bp = Bw + (size_t)z * sB;

    const int ar = tid & 127, acb = (tid >> 7) * 4;
    const int NCH = K >> 6;

    float acc[2][8][4];
#pragma unroll
    for (int i = 0; i < 2; i++)
#pragma unroll
        for (int j = 0; j < 8; j++)
#pragma unroll
            for (int r = 0; r < 4; r++) acc[i][j][r] = 0.0f;

    auto load_chunk = [&](int stage, int ch) {
        const uint32_t Abase = sbase + stage * STAGE_BYTES;
        const uint32_t Bbase = Abase + 16384;
        const __half* ga = Ab + (size_t)(m0 + ar) * K + ch * 64 + acb * 8;
        const __half* gb = Bp + (size_t)(n0 + ar) * K + ch * 64 + acb * 8;
#pragma unroll
        for (int j = 0; j < 4; j++) {
            int c = acb + j;
            uint32_t sw = ((uint32_t)(c ^ (ar & 7))) << 4;
            cpa16(Abase + ar * 128 + sw, ga + j * 8);
            cpa16(Bbase + ar * 128 + sw, gb + j * 8);
        }
    };

    auto compute = [&](int stage) {
        const uint32_t Abase = sbase + stage * STAGE_BYTES;
        const uint32_t Bbase = Abase + 16384;
#pragma unroll
        for (int s16 = 0; s16 < 4; s16++) {
            uint32_t a[2][4];
#pragma unroll
            for (int mi = 0; mi < 2; mi++) {
                int row = wm + mi * 16 + (lane & 15);
                int c = s16 * 2 + (lane >> 4);
                ldm4(a[mi], Abase + row * 128 + (((uint32_t)(c ^ (row & 7))) << 4));
            }
            uint32_t bf[4][4];
#pragma unroll
            for (int nb = 0; nb < 4; nb++) {
                int row = wn + nb * 16 + (lane & 15);
                int c = s16 * 2 + (lane >> 4);
                ldm4(bf[nb], Bbase + row * 128 + (((uint32_t)(c ^ (row & 7))) << 4));
            }
#pragma unroll
            for (int mi = 0; mi < 2; mi++)
#pragma unroll
                for (int nb = 0; nb < 4; nb++) {
                    uint32_t b0[2] = {bf[nb][0], bf[nb][2]};
                    uint32_t b1[2] = {bf[nb][1], bf[nb][3]};
                    mma16(acc[mi][2 * nb], a[mi], b0);
                    mma16(acc[mi][2 * nb + 1], a[mi], b1);
                }
        }
    };

    load_chunk(0, 0);
    CPA_COMMIT();
    for (int i = 0; i < NCH; i++) {
        if (i + 1 < NCH) {
            load_chunk((i + 1) & 1, i + 1);
            CPA_COMMIT();
            CPA_WAIT1();
        } else {
            CPA_WAIT0();
        }
        __syncthreads();
        compute(i & 1);
        __syncthreads();
    }

    // ---------------- epilogue ----------------
    const int g = lane >> 2, tg = lane & 3;
#pragma unroll
    for (int mi = 0; mi < 2; mi++) {
#pragma unroll
        for (int ni = 0; ni < 8; ni++) {
            int n = n0 + wn + ni * 8 + 2 * tg;
#pragma unroll
            for (int hh = 0; hh < 2; hh++) {
                int m = m0 + wm + mi * 16 + g + hh * 8;
                size_t off = (size_t)z * sC + (size_t)m * ldc + n;
#pragma unroll
                for (int jj = 0; jj < 2; jj++) {
                    float v = acc[mi][ni][hh * 2 + jj];
                    size_t o = off + jj;
                    int nn = n + jj;
                    if (EPI == 0) {
                        ((float*)Cout)[o] = (v >= 0.0f) ? v : 0.1f * v;
                    } else if (EPI == 1) {
                        float t = qsrc[o] - v;
                        ((__half*)Cout)[o] = __float2half_rn(t * t);
                    } else if (EPI == 2) {
                        ((float*)Cout)[o] = v;
                    } else if (EPI == 3) {
                        ((float*)Cout)[o] = v + __ldg(bias + nn);
                    } else if (EPI == 4) {
                        ((__half*)Cout)[o] = __float2half_rn(tanhf(v + __ldg(bias + nn)));
                    } else {
                        float t = tanhf(v + __ldg(bias + nn));
                        float nm = fminf(1.0f, fmaxf(-1.0f, t + mat[o]));
                        mat[o] = nm;
                        qm16[o] = __float2half_rn(qsrc[o] * nm);
                    }
                }
            }
        }
    }
}

// ---------------- transpose f32 [R][C] -> f16 [C][R] (batched) ----------------
// launch grid: (C/32, R/32, batch)
__global__ void transpose_f2h(const float* __restrict__ src, __half* __restrict__ dst,
                              int R, int C, size_t sSrc, size_t sDst)
{
    __shared__ float t[32][33];
    const float* s = src + (size_t)blockIdx.z * sSrc;
    __half* d = dst + (size_t)blockIdx.z * sDst;
    int r0 = blockIdx.y * 32, c0 = blockIdx.x * 32;
    for (int j = threadIdx.y; j < 32; j += 8)
        t[j][threadIdx.x] = s[(size_t)(r0 + j) * C + c0 + threadIdx.x];
    __syncthreads();
    for (int j = threadIdx.y; j < 32; j += 8)
        d[(size_t)(c0 + j) * R + r0 + threadIdx.x] = __float2half_rn(t[threadIdx.x][j]);
}

// ---------------- elementwise kernels ----------------
__global__ void init_kernel(const float* __restrict__ query,
                            float* __restrict__ matrix, float* __restrict__ smooth,
                            __half* __restrict__ qm16) {
    size_t i = (size_t)blockIdx.x * blockDim.x + threadIdx.x;
    if (i < (size_t)Bb * NQ * D) {
        matrix[i] = 1.0f;
        qm16[i] = __float2half_rn(query[i]);
    }
    if (i < (size_t)Bb * NQ) smooth[i] = 10.0f;
}

__global__ void convert_kernel(const float* __restrict__ src, __half* __restrict__ dst, int n) {
    int i = blockIdx.x * blockDim.x + threadIdx.x;
    if (i < n) dst[i] = __float2half_rn(src[i]);
}

__global__ void rownorm_kernel(const float* __restrict__ S, float* __restrict__ invn) {
    int bc = blockIdx.x;
    float v = S[(size_t)bc * NQ + threadIdx.x];
    float s = warp_sum(v * v);
    __shared__ float red[8];
    if ((threadIdx.x & 31) == 0) red[threadIdx.x >> 5] = s;
    __syncthreads();
    if (threadIdx.x == 0) {
        float t = red[0] + red[1] + red[2] + red[3] + red[4] + red[5] + red[6] + red[7];
        invn[bc] = 1.0f / (sqrtf(t) + 1e-8f);
    }
}

__global__ void __launch_bounds__(256) softmax_kernel(
    const float* __restrict__ S, const float* __restrict__ invn,
    const float* __restrict__ smooth, __half* __restrict__ a16,
    float* __restrict__ a32)
{
    int b = blockIdx.y;
    int q0 = blockIdx.x * 32;
    __shared__ float sm[NC][33];
    const float* Sb = S + (size_t)b * NC * NQ;
    for (int idx = threadIdx.x; idx < NC * 32; idx += 256) {
        int c = idx >> 5, qq = idx & 31;
        sm[c][qq] = Sb[(size_t)c * NQ + q0 + qq] * invn[b * NC + c];
    }
    __syncthreads();
    int warp = threadIdx.x >> 5, lane = threadIdx.x & 31;
    for (int qi = warp; qi < 32; qi += 8) {
        float sf = smooth[b * NQ + q0 + qi];
        float v0 = sm[lane][qi] * sf;
        float v1 = sm[lane + 32][qi] * sf;
        float v2 = sm[lane + 64][qi] * sf;
        float v3 = sm[lane + 96][qi] * sf;
        float mx = fmaxf(fmaxf(v0, v1), fmaxf(v2, v3));
#pragma unroll
        for (int o = 16; o > 0; o >>= 1) mx = fmaxf(mx, __shfl_xor_sync(0xffffffffu, mx, o));
        float e0 = expf(v0 - mx), e1 = expf(v1 - mx), e2 = expf(v2 - mx), e3 = expf(v3 - mx);
        float s = warp_sum(e0 + e1 + e2 + e3);
        float inv = 1.0f / s;
        size_t base = ((size_t)b * NQ + q0 + qi) * NC;
        a16[base + lane]      = __float2half_rn(e0 * inv);
        a16[base + lane + 32] = __float2half_rn(e1 * inv);
        a16[base + lane + 64] = __float2half_rn(e2 * inv);
        a16[base + lane + 96] = __float2half_rn(e3 * inv);
        if (a32) {
            a32[base + lane]      = e0 * inv;
            a32[base + lane + 32] = e1 * inv;
            a32[base + lane + 64] = e2 * inv;
            a32[base + lane + 96] = e3 * inv;
        }
    }
}

__global__ void l2norm256_kernel(const float* __restrict__ X, __half* __restrict__ Y) {
    const float* p = X + (size_t)blockIdx.x * AD;
    float v = p[threadIdx.x];
    float s = warp_sum(v * v);
    __shared__ float red[8];
    if ((threadIdx.x & 31) == 0) red[threadIdx.x >> 5] = s;
    __syncthreads();
    float t = red[0] + red[1] + red[2] + red[3] + red[4] + red[5] + red[6] + red[7];
    Y[(size_t)blockIdx.x * AD + threadIdx.x] = __float2half_rn(v / (sqrtf(t) + 1e-8f));
}

__global__ void sw_reduce_kernel(const __half* __restrict__ sh, const float* __restrict__ w2,
                                 const float* __restrict__ b2, float* __restrict__ smooth)
{
    int row = blockIdx.x * 8 + (threadIdx.x >> 5);
    int lane = threadIdx.x & 31;
    const __half* r = sh + (size_t)row * HD;
    float s = __half2float(r[lane]) * w2[lane]
            + __half2float(r[lane + 32]) * w2[lane + 32]
            + __half2float(r[lane + 64]) * w2[lane + 64]
            + __half2float(r[lane + 96]) * w2[lane + 96];
    s = warp_sum(s);
    if (lane == 0) smooth[row] = fmaxf(0.0f, s + b2[0] + smooth[row]);
}

// ---------------- orchestration ----------------
extern "C" void kernel_launch(void* const* d_in, const int* in_sizes, int n_in,
                              void* d_out, int out_size)
{
    const float* query = (const float*)d_in[0];
    const float* ctx   = (const float*)d_in[1];
    const float* cw_W  = (const float*)d_in[2];
    const float* cw_b  = (const float*)d_in[3];
    const float* sw_W1 = (const float*)d_in[4];
    const float* sw_b1 = (const float*)d_in[5];
    const float* sw_W2 = (const float*)d_in[6];
    const float* sw_b2 = (const float*)d_in[7];
    const float* mw_W1 = (const float*)d_in[8];
    const float* mw_b1 = (const float*)d_in[9];
    const float* mw_W2 = (const float*)d_in[10];
    const float* mw_b2 = (const float*)d_in[11];

    float* out      = (float*)d_out;
    float* out_q    = out;
    float* out_wc   = out + (size_t)Bb * NQ * D;
    float* out_attn = out + 2 * (size_t)Bb * NQ * D;

    float *pS, *pinvn, *pmat, *psm, *pcom;
    __half *pqm, *pctx16, *pctxT, *pattn16, *pd16, *pcom16, *ph16, *psh16, *pw16;
    cudaGetSymbolAddress((void**)&pS,      g_S);
    cudaGetSymbolAddress((void**)&pinvn,   g_invn);
    cudaGetSymbolAddress((void**)&pmat,    g_matrix);
    cudaGetSymbolAddress((void**)&psm,     g_smooth);
    cudaGetSymbolAddress((void**)&pcom,    g_common);
    cudaGetSymbolAddress((void**)&pqm,     g_qm16);
    cudaGetSymbolAddress((void**)&pctx16,  g_ctx16);
    cudaGetSymbolAddress((void**)&pctxT,   g_ctxT16);
    cudaGetSymbolAddress((void**)&pattn16, g_attn16);
    cudaGetSymbolAddress((void**)&pd16,    g_d16);
    cudaGetSymbolAddress((void**)&pcom16,  g_com16);
    cudaGetSymbolAddress((void**)&ph16,    g_h16);
    cudaGetSymbolAddress((void**)&psh16,   g_sh16);
    cudaGetSymbolAddress((void**)&pw16,    g_w16);

    cudaFuncSetAttribute(hgemm<0>, cudaFuncAttributeMaxDynamicSharedMemorySize, SMEM_BYTES);
    cudaFuncSetAttribute(hgemm<1>, cudaFuncAttributeMaxDynamicSharedMemorySize, SMEM_BYTES);
    cudaFuncSetAttribute(hgemm<2>, cudaFuncAttributeMaxDynamicSharedMemorySize, SMEM_BYTES);
    cudaFuncSetAttribute(hgemm<3>, cudaFuncAttributeMaxDynamicSharedMemorySize, SMEM_BYTES);
    cudaFuncSetAttribute(hgemm<4>, cudaFuncAttributeMaxDynamicSharedMemorySize, SMEM_BYTES);
    cudaFuncSetAttribute(hgemm<5>, cudaFuncAttributeMaxDynamicSharedMemorySize, SMEM_BYTES);

    // init + conversions + transposes (weights -> [n][k] fp16; ctx -> both layouts)
    init_kernel<<<(Bb * NQ * D + 255) / 256, 256>>>(query, pmat, psm, pqm);
    convert_kernel<<<(Bb * NC * D + 255) / 256, 256>>>(ctx, pctx16, Bb * NC * D);
    // ctx [c][d] -> ctxT [d][c]: R=NC rows, C=D cols, grid = (C/32, R/32, batch)
    transpose_f2h<<<dim3(D / 32, NC / 32, Bb), dim3(32, 8)>>>(
        ctx, pctxT, NC, D, (size_t)NC * D, (size_t)NC * D);
    transpose_f2h<<<dim3(AD / 32, D / 32, 2), dim3(32, 8)>>>(
        cw_W, pw16 + W_CW, D, AD, (size_t)D * AD, (size_t)D * AD);
    transpose_f2h<<<dim3(HD / 32, AD / 32, 2), dim3(32, 8)>>>(
        sw_W1, pw16 + W_SW1, AD, HD, (size_t)AD * HD, (size_t)AD * HD);
    transpose_f2h<<<dim3(MD / 32, AD / 32, 2), dim3(32, 8)>>>(
        mw_W1, pw16 + W_MW1, AD, MD, (size_t)AD * MD, (size_t)AD * MD);
    transpose_f2h<<<dim3(D / 32, MD / 32, 2), dim3(32, 8)>>>(
        mw_W2, pw16 + W_MW2, MD, D, (size_t)MD * D, (size_t)MD * D);

    for (int i = 0; i < 2; i++) {
        // S = leaky(ctx @ qm^T): A=ctx16 [c][d], B=qm16 [q][d]
        hgemm<0><<<dim3(2, 1, Bb), 256, SMEM_BYTES>>>(
            pctx16, pqm, nullptr, pS, nullptr, nullptr, nullptr,
            D, NQ, (size_t)NC * D, (size_t)NQ * D, (size_t)NC * NQ);
        rownorm_kernel<<<Bb * NC, 256>>>(pS, pinvn);
        softmax_kernel<<<dim3(8, Bb), 256>>>(pS, pinvn, psm, pattn16, nullptr);
        // d16 = (q - attn@ctx)^2: A=attn16 [q][c], B=ctxT [d][c]
        hgemm<1><<<dim3(8, 2, Bb), 256, SMEM_BYTES>>>(
            pattn16, pctxT, nullptr, pd16, query, nullptr, nullptr,
            NC, D, (size_t)NQ * NC, (size_t)NC * D, (size_t)NQ * D);
        // common = d16 @ cw_W + b: B=cwT [ad][d]
        hgemm<3><<<dim3(2, 256, 1), 256, SMEM_BYTES>>>(
            pd16, pw16 + W_CW + (size_t)i * D * AD, cw_b + (size_t)i * AD, pcom,
            nullptr, nullptr, nullptr, D, AD, 0, 0, 0);
        l2norm256_kernel<<<Bb * NQ, 256>>>(pcom, pcom16);
        // smooth branch
        hgemm<4><<<dim3(1, 256, 1), 256, SMEM_BYTES>>>(
            pcom16, pw16 + W_SW1 + (size_t)i * AD * HD, sw_b1 + (size_t)i * HD, psh16,
            nullptr, nullptr, nullptr, AD, HD, 0, 0, 0);
        sw_reduce_kernel<<<Bb * NQ / 8, 256>>>(psh16, sw_W2 + (size_t)i * HD, sw_b2 + i, psm);
        // matrix branch
        hgemm<4><<<dim3(4, 256, 1), 256, SMEM_BYTES>>>(
            pcom16, pw16 + W_MW1 + (size_t)i * AD * MD, mw_b1 + (size_t)i * MD, ph16,
            nullptr, nullptr, nullptr, AD, MD, 0, 0, 0);
        hgemm<5><<<dim3(8, 256, 1), 256, SMEM_BYTES>>>(
            ph16, pw16 + W_MW2 + (size_t)i * MD * D, mw_b2 + (size_t)i * D, nullptr,
            query, pmat, pqm, MD, D, 0, 0, 0);
    }

    // final scan -> d_out
    hgemm<0><<<dim3(2, 1, Bb), 256, SMEM_BYTES>>>(
        pctx16, pqm, nullptr, pS, nullptr, nullptr, nullptr,
        D, NQ, (size_t)NC * D, (size_t)NQ * D, (size_t)NC * NQ);
    rownorm_kernel<<<Bb * NC, 256>>>(pS, pinvn);
    softmax_kernel<<<dim3(8, Bb), 256>>>(pS, pinvn, psm, pattn16, out_attn);
    hgemm<2><<<dim3(8, 2, Bb), 256, SMEM_BYTES>>>(
        pattn16, pctxT, nullptr, out_wc, nullptr, nullptr, nullptr,
        NC, D, (size_t)NQ * NC, (size_t)NC * D, (size_t)NQ * D);

    cudaMemcpyAsync(out_q, query, (size_t)Bb * NQ * D * sizeof(float),
                    cudaMemcpyDeviceToDevice, 0);
}

// round 8
// speedup vs baseline: 1.9921x; 1.2302x over previous
#include <cuda_runtime.h>
#include <cuda_fp16.h>
#include <stdint.h>
#include <math.h>

// Problem constants
#define Bb 128
#define NQ 256
#define NC 128
#define D  1024
#define AD 256
#define HD 128
#define MD 512

// transposed weight pack offsets (halves)
#define W_CW  0
#define W_SW1 (W_CW  + 2 * D * AD)
#define W_MW1 (W_SW1 + 2 * AD * HD)
#define W_MW2 (W_MW1 + 2 * AD * MD)
#define W_TOT (W_MW2 + 2 * MD * D)

// ---------------- scratch (device globals) ----------------
__device__ float  g_S[Bb * NC * NQ];
__device__ float  g_matrix[Bb * NQ * D];
__device__ float  g_smooth[Bb * NQ];
__device__ float  g_common[Bb * NQ * AD];
__device__ __half g_qm16[Bb * NQ * D];
__device__ __half g_ctx16[Bb * NC * D];    // [b][c][d]
__device__ __half g_ctxT16[Bb * D * NC];   // [b][d][c]
__device__ __half g_attn16[Bb * NQ * NC];
__device__ __half g_d16[Bb * NQ * D];
__device__ __half g_com16[Bb * NQ * AD];
__device__ __half g_h16[Bb * NQ * MD];
__device__ __half g_sh16[Bb * NQ * HD];
__device__ __half g_w16[W_TOT];            // all weights transposed to [n][k]

// ---------------- utils ----------------
__device__ __forceinline__ float warp_sum(float v) {
#pragma unroll
    for (int o = 16; o > 0; o >>= 1) v += __shfl_xor_sync(0xffffffffu, v, o);
    return v;
}

__device__ __forceinline__ uint32_t smem_u32(const void* p) {
    uint32_t a;
    asm("{ .reg .u64 t; cvta.to.shared.u64 t, %1; cvt.u32.u64 %0, t; }" : "=r"(a) : "l"(p));
    return a;
}

__device__ __forceinline__ void cpa16(uint32_t dst, const void* src) {
    asm volatile("cp.async.cg.shared.global [%0], [%1], 16;" :: "r"(dst), "l"(src));
}
#define CPA_COMMIT() asm volatile("cp.async.commit_group;" ::: "memory")
#define CPA_WAIT1()  asm volatile("cp.async.wait_group 1;" ::: "memory")
#define CPA_WAIT0()  asm volatile("cp.async.wait_group 0;" ::: "memory")

__device__ __forceinline__ void ldm4(uint32_t* r, uint32_t a) {
    asm volatile("ldmatrix.sync.aligned.m8n8.x4.shared.b16 {%0,%1,%2,%3}, [%4];"
        : "=r"(r[0]), "=r"(r[1]), "=r"(r[2]), "=r"(r[3]) : "r"(a));
}

__device__ __forceinline__ void mma16(float* c, const uint32_t* a, const uint32_t* b) {
    asm volatile(
        "mma.sync.aligned.m16n8k16.row.col.f32.f16.f16.f32 "
        "{%0,%1,%2,%3},{%4,%5,%6,%7},{%8,%9},{%0,%1,%2,%3};"
        : "+f"(c[0]), "+f"(c[1]), "+f"(c[2]), "+f"(c[3])
        : "r"(a[0]), "r"(a[1]), "r"(a[2]), "r"(a[3]), "r"(b[0]), "r"(b[1]));
}

#define STAGE_BYTES 32768
#define SMEM_BYTES  (3 * STAGE_BYTES)

// ---------------- pipelined fp16 GEMM: 3-stage cp.async ring, 1 sync/chunk -----
// Tile 128(M) x 128(N), K chunks of 64 halves (128B rows), 2 CTA/SM.
// EPI: 0 leaky->f32 | 1 (q-v)^2->half | 2 plain f32 | 3 +bias f32
//      4 tanh(v+bias)->half | 5 matrix update + qm16
template<int EPI>
__global__ void __launch_bounds__(256, 2) hgemm(
    const __half* __restrict__ A, const __half* __restrict__ Bw,
    const float* __restrict__ bias, void* __restrict__ Cout,
    const float* __restrict__ qsrc, float* __restrict__ mat,
    __half* __restrict__ qm16,
    int K, int ldc, size_t sA, size_t sB, size_t sC)
{
    extern __shared__ __half smemh[];
    const uint32_t sbase = smem_u32(smemh);

    const int tid = threadIdx.x;
    const int lane = tid & 31, warp = tid >> 5;
    const int wm = (warp & 3) * 32, wn = (warp >> 2) * 64;
    const int z = blockIdx.z;
    const int m0 = blockIdx.y * 128, n0 = blockIdx.x * 128;

    const __half* Ab = A + (size_t)z * sA;
    const __half* Bp = Bw + (size_t)z * sB;

    const int ar = tid & 127, acb = (tid >> 7) * 4;
    const int NCH = K >> 6;

    float acc[2][8][4];
#pragma unroll
    for (int i = 0; i < 2; i++)
#pragma unroll
        for (int j = 0; j < 8; j++)
#pragma unroll
            for (int r = 0; r < 4; r++) acc[i][j][r] = 0.0f;

    auto load_chunk = [&](int stage, int ch) {
        const uint32_t Abase = sbase + stage * STAGE_BYTES;
        const uint32_t Bbase = Abase + 16384;
        const __half* ga = Ab + (size_t)(m0 + ar) * K + ch * 64 + acb * 8;
        const __half* gb = Bp + (size_t)(n0 + ar) * K + ch * 64 + acb * 8;
#pragma unroll
        for (int j = 0; j < 4; j++) {
            int c = acb + j;
            uint32_t sw = ((uint32_t)(c ^ (ar & 7))) << 4;
            cpa16(Abase + ar * 128 + sw, ga + j * 8);
            cpa16(Bbase + ar * 128 + sw, gb + j * 8);
        }
    };

    auto compute = [&](int stage) {
        const uint32_t Abase = sbase + stage * STAGE_BYTES;
        const uint32_t Bbase = Abase + 16384;
#pragma unroll
        for (int s16 = 0; s16 < 4; s16++) {
            uint32_t a[2][4];
#pragma unroll
            for (int mi = 0; mi < 2; mi++) {
                int row = wm + mi * 16 + (lane & 15);
                int c = s16 * 2 + (lane >> 4);
                ldm4(a[mi], Abase + row * 128 + (((uint32_t)(c ^ (row & 7))) << 4));
            }
            uint32_t bf[4][4];
#pragma unroll
            for (int nb = 0; nb < 4; nb++) {
                int row = wn + nb * 16 + (lane & 15);
                int c = s16 * 2 + (lane >> 4);
                ldm4(bf[nb], Bbase + row * 128 + (((uint32_t)(c ^ (row & 7))) << 4));
            }
#pragma unroll
            for (int mi = 0; mi < 2; mi++)
#pragma unroll
                for (int nb = 0; nb < 4; nb++) {
                    uint32_t b0[2] = {bf[nb][0], bf[nb][2]};
                    uint32_t b1[2] = {bf[nb][1], bf[nb][3]};
                    mma16(acc[mi][2 * nb], a[mi], b0);
                    mma16(acc[mi][2 * nb + 1], a[mi], b1);
                }
        }
    };

    // prologue: 2 chunks in flight
    load_chunk(0, 0);
    CPA_COMMIT();
    if (NCH > 1) { load_chunk(1, 1); CPA_COMMIT(); }

    for (int i = 0; i < NCH; i++) {
        if (i + 2 < NCH) { CPA_WAIT1(); } else { CPA_WAIT0(); }
        __syncthreads();
        if (i + 2 < NCH) {
            load_chunk((i + 2) % 3, i + 2);
            CPA_COMMIT();
        }
        compute(i % 3);
    }

    // ---------------- epilogue (vectorized stores) ----------------
    const int g = lane >> 2, tg = lane & 3;
#pragma unroll
    for (int mi = 0; mi < 2; mi++) {
#pragma unroll
        for (int ni = 0; ni < 8; ni++) {
            int n = n0 + wn + ni * 8 + 2 * tg;
#pragma unroll
            for (int hh = 0; hh < 2; hh++) {
                int m = m0 + wm + mi * 16 + g + hh * 8;
                size_t o = (size_t)z * sC + (size_t)m * ldc + n;
                float v0 = acc[mi][ni][hh * 2 + 0];
                float v1 = acc[mi][ni][hh * 2 + 1];
                if (EPI == 0) {
                    float2 w;
                    w.x = (v0 >= 0.0f) ? v0 : 0.1f * v0;
                    w.y = (v1 >= 0.0f) ? v1 : 0.1f * v1;
                    *(float2*)((float*)Cout + o) = w;
                } else if (EPI == 1) {
                    float2 q = *(const float2*)(qsrc + o);
                    float t0 = q.x - v0, t1 = q.y - v1;
                    *(__half2*)((__half*)Cout + o) = __floats2half2_rn(t0 * t0, t1 * t1);
                } else if (EPI == 2) {
                    float2 w = {v0, v1};
                    *(float2*)((float*)Cout + o) = w;
                } else if (EPI == 3) {
                    float2 w = {v0 + __ldg(bias + n), v1 + __ldg(bias + n + 1)};
                    *(float2*)((float*)Cout + o) = w;
                } else if (EPI == 4) {
                    *(__half2*)((__half*)Cout + o) =
                        __floats2half2_rn(tanhf(v0 + __ldg(bias + n)),
                                          tanhf(v1 + __ldg(bias + n + 1)));
                } else {
                    float2 old = *(float2*)(mat + o);
                    float2 q = *(const float2*)(qsrc + o);
                    float n0v = fminf(1.0f, fmaxf(-1.0f, tanhf(v0 + __ldg(bias + n)) + old.x));
                    float n1v = fminf(1.0f, fmaxf(-1.0f, tanhf(v1 + __ldg(bias + n + 1)) + old.y));
                    float2 w = {n0v, n1v};
                    *(float2*)(mat + o) = w;
                    *(__half2*)(qm16 + o) = __floats2half2_rn(q.x * n0v, q.y * n1v);
                }
            }
        }
    }
}

// ---------------- fused rownorm + softmax (one CTA per batch) ----------------
// S[b]: [NC][NQ] f32.  invn over q per c, then softmax over c per q (x smooth).
#define SMS_STRIDE 257
#define SMS_BYTES  ((NC * SMS_STRIDE + NC) * 4)
__global__ void __launch_bounds__(256) normsoftmax_kernel(
    const float* __restrict__ S, const float* __restrict__ smooth,
    __half* __restrict__ a16, float* __restrict__ a32)
{
    extern __shared__ float sm[];          // [NC][SMS_STRIDE] + invn[NC]
    float* sinv = sm + NC * SMS_STRIDE;
    const int b = blockIdx.x;
    const int tid = threadIdx.x;
    const int warp = tid >> 5, lane = tid & 31;

    const float4* Sb = (const float4*)(S + (size_t)b * NC * NQ);
    for (int idx = tid; idx < NC * NQ / 4; idx += 256) {
        int c = idx >> 6;             // 64 float4 per row
        int q4 = idx & 63;
        float4 v = Sb[idx];
        float* p = sm + c * SMS_STRIDE + q4 * 4;
        p[0] = v.x; p[1] = v.y; p[2] = v.z; p[3] = v.w;
    }
    __syncthreads();

    // row norms over q: warp w -> rows w*16 .. w*16+15
#pragma unroll
    for (int r = 0; r < 16; r++) {
        int c = warp * 16 + r;
        const float* p = sm + c * SMS_STRIDE;
        float s = 0.0f;
#pragma unroll
        for (int j = 0; j < 8; j++) {
            float x = p[lane + 32 * j];
            s += x * x;
        }
        s = warp_sum(s);
        if (lane == 0) sinv[c] = 1.0f / (sqrtf(s) + 1e-8f);
    }
    __syncthreads();

    // softmax over c: warp handles q = warp, warp+8, ...
    for (int qi = warp; qi < NQ; qi += 8) {
        float sf = smooth[b * NQ + qi];
        float v0 = sm[(lane)      * SMS_STRIDE + qi] * sinv[lane]      * sf;
        float v1 = sm[(lane + 32) * SMS_STRIDE + qi] * sinv[lane + 32] * sf;
        float v2 = sm[(lane + 64) * SMS_STRIDE + qi] * sinv[lane + 64] * sf;
        float v3 = sm[(lane + 96) * SMS_STRIDE + qi] * sinv[lane + 96] * sf;
        float mx = fmaxf(fmaxf(v0, v1), fmaxf(v2, v3));
#pragma unroll
        for (int o = 16; o > 0; o >>= 1) mx = fmaxf(mx, __shfl_xor_sync(0xffffffffu, mx, o));
        float e0 = expf(v0 - mx), e1 = expf(v1 - mx), e2 = expf(v2 - mx), e3 = expf(v3 - mx);
        float s = warp_sum(e0 + e1 + e2 + e3);
        float inv = 1.0f / s;
        size_t base = ((size_t)b * NQ + qi) * NC;
        a16[base + lane]      = __float2half_rn(e0 * inv);
        a16[base + lane + 32] = __float2half_rn(e1 * inv);
        a16[base + lane + 64] = __float2half_rn(e2 * inv);
        a16[base + lane + 96] = __float2half_rn(e3 * inv);
        if (a32) {
            a32[base + lane]      = e0 * inv;
            a32[base + lane + 32] = e1 * inv;
            a32[base + lane + 64] = e2 * inv;
            a32[base + lane + 96] = e3 * inv;
        }
    }
}

// ---------------- transpose f32 [R][C] -> f16 [C][R] (batched) ----------------
// launch grid: (C/32, R/32, batch)
__global__ void transpose_f2h(const float* __restrict__ src, __half* __restrict__ dst,
                              int R, int C, size_t sSrc, size_t sDst)
{
    __shared__ float t[32][33];
    const float* s = src + (size_t)blockIdx.z * sSrc;
    __half* d = dst + (size_t)blockIdx.z * sDst;
    int r0 = blockIdx.y * 32, c0 = blockIdx.x * 32;
    for (int j = threadIdx.y; j < 32; j += 8)
        t[j][threadIdx.x] = s[(size_t)(r0 + j) * C + c0 + threadIdx.x];
    __syncthreads();
    for (int j = threadIdx.y; j < 32; j += 8)
        d[(size_t)(c0 + j) * R + r0 + threadIdx.x] = __float2half_rn(t[threadIdx.x][j]);
}

// ---------------- elementwise kernels ----------------
__global__ void init_kernel(const float* __restrict__ query,
                            float* __restrict__ matrix, float* __restrict__ smooth,
                            __half* __restrict__ qm16) {
    size_t i = ((size_t)blockIdx.x * blockDim.x + threadIdx.x) * 4;
    if (i < (size_t)Bb * NQ * D) {
        float4 q = *(const float4*)(query + i);
        float4 one = {1.0f, 1.0f, 1.0f, 1.0f};
        *(float4*)(matrix + i) = one;
        __half2 h0 = __floats2half2_rn(q.x, q.y);
        __half2 h1 = __floats2half2_rn(q.z, q.w);
        *(__half2*)(qm16 + i) = h0;
        *(__half2*)(qm16 + i + 2) = h1;
    }
    if (i < (size_t)Bb * NQ * 4) {
        size_t j = i / 4;
        smooth[j] = 10.0f;
    }
}

__global__ void convert_kernel(const float* __restrict__ src, __half* __restrict__ dst, int n) {
    int i = (blockIdx.x * blockDim.x + threadIdx.x) * 4;
    if (i < n) {
        float4 v = *(const float4*)(src + i);
        *(__half2*)(dst + i)     = __floats2half2_rn(v.x, v.y);
        *(__half2*)(dst + i + 2) = __floats2half2_rn(v.z, v.w);
    }
}

__global__ void l2norm256_kernel(const float* __restrict__ X, __half* __restrict__ Y) {
    const float* p = X + (size_t)blockIdx.x * AD;
    float v = p[threadIdx.x];
    float s = warp_sum(v * v);
    __shared__ float red[8];
    if ((threadIdx.x & 31) == 0) red[threadIdx.x >> 5] = s;
    __syncthreads();
    float t = red[0] + red[1] + red[2] + red[3] + red[4] + red[5] + red[6] + red[7];
    Y[(size_t)blockIdx.x * AD + threadIdx.x] = __float2half_rn(v / (sqrtf(t) + 1e-8f));
}

__global__ void sw_reduce_kernel(const __half* __restrict__ sh, const float* __restrict__ w2,
                                 const float* __restrict__ b2, float* __restrict__ smooth)
{
    int row = blockIdx.x * 8 + (threadIdx.x >> 5);
    int lane = threadIdx.x & 31;
    const __half* r = sh + (size_t)row * HD;
    float s = __half2float(r[lane]) * w2[lane]
            + __half2float(r[lane + 32]) * w2[lane + 32]
            + __half2float(r[lane + 64]) * w2[lane + 64]
            + __half2float(r[lane + 96]) * w2[lane + 96];
    s = warp_sum(s);
    if (lane == 0) smooth[row] = fmaxf(0.0f, s + b2[0] + smooth[row]);
}

// ---------------- orchestration ----------------
extern "C" void kernel_launch(void* const* d_in, const int* in_sizes, int n_in,
                              void* d_out, int out_size)
{
    const float* query = (const float*)d_in[0];
    const float* ctx   = (const float*)d_in[1];
    const float* cw_W  = (const float*)d_in[2];
    const float* cw_b  = (const float*)d_in[3];
    const float* sw_W1 = (const float*)d_in[4];
    const float* sw_b1 = (const float*)d_in[5];
    const float* sw_W2 = (const float*)d_in[6];
    const float* sw_b2 = (const float*)d_in[7];
    const float* mw_W1 = (const float*)d_in[8];
    const float* mw_b1 = (const float*)d_in[9];
    const float* mw_W2 = (const float*)d_in[10];
    const float* mw_b2 = (const float*)d_in[11];

    float* out      = (float*)d_out;
    float* out_q    = out;
    float* out_wc   = out + (size_t)Bb * NQ * D;
    float* out_attn = out + 2 * (size_t)Bb * NQ * D;

    float *pS, *pmat, *psm, *pcom;
    __half *pqm, *pctx16, *pctxT, *pattn16, *pd16, *pcom16, *ph16, *psh16, *pw16;
    cudaGetSymbolAddress((void**)&pS,      g_S);
    cudaGetSymbolAddress((void**)&pmat,    g_matrix);
    cudaGetSymbolAddress((void**)&psm,     g_smooth);
    cudaGetSymbolAddress((void**)&pcom,    g_common);
    cudaGetSymbolAddress((void**)&pqm,     g_qm16);
    cudaGetSymbolAddress((void**)&pctx16,  g_ctx16);
    cudaGetSymbolAddress((void**)&pctxT,   g_ctxT16);
    cudaGetSymbolAddress((void**)&pattn16, g_attn16);
    cudaGetSymbolAddress((void**)&pd16,    g_d16);
    cudaGetSymbolAddress((void**)&pcom16,  g_com16);
    cudaGetSymbolAddress((void**)&ph16,    g_h16);
    cudaGetSymbolAddress((void**)&psh16,   g_sh16);
    cudaGetSymbolAddress((void**)&pw16,    g_w16);

    cudaFuncSetAttribute(hgemm<0>, cudaFuncAttributeMaxDynamicSharedMemorySize, SMEM_BYTES);
    cudaFuncSetAttribute(hgemm<1>, cudaFuncAttributeMaxDynamicSharedMemorySize, SMEM_BYTES);
    cudaFuncSetAttribute(hgemm<2>, cudaFuncAttributeMaxDynamicSharedMemorySize, SMEM_BYTES);
    cudaFuncSetAttribute(hgemm<3>, cudaFuncAttributeMaxDynamicSharedMemorySize, SMEM_BYTES);
    cudaFuncSetAttribute(hgemm<4>, cudaFuncAttributeMaxDynamicSharedMemorySize, SMEM_BYTES);
    cudaFuncSetAttribute(hgemm<5>, cudaFuncAttributeMaxDynamicSharedMemorySize, SMEM_BYTES);
    cudaFuncSetAttribute(normsoftmax_kernel, cudaFuncAttributeMaxDynamicSharedMemorySize, SMS_BYTES);

    // init + conversions + transposes
    init_kernel<<<(Bb * NQ * D / 4 + 255) / 256, 256>>>(query, pmat, psm, pqm);
    convert_kernel<<<(Bb * NC * D / 4 + 255) / 256, 256>>>(ctx, pctx16, Bb * NC * D);
    transpose_f2h<<<dim3(D / 32, NC / 32, Bb), dim3(32, 8)>>>(
        ctx, pctxT, NC, D, (size_t)NC * D, (size_t)NC * D);
    transpose_f2h<<<dim3(AD / 32, D / 32, 2), dim3(32, 8)>>>(
        cw_W, pw16 + W_CW, D, AD, (size_t)D * AD, (size_t)D * AD);
    transpose_f2h<<<dim3(HD / 32, AD / 32, 2), dim3(32, 8)>>>(
        sw_W1, pw16 + W_SW1, AD, HD, (size_t)AD * HD, (size_t)AD * HD);
    transpose_f2h<<<dim3(MD / 32, AD / 32, 2), dim3(32, 8)>>>(
        mw_W1, pw16 + W_MW1, AD, MD, (size_t)AD * MD, (size_t)AD * MD);
    transpose_f2h<<<dim3(D / 32, MD / 32, 2), dim3(32, 8)>>>(
        mw_W2, pw16 + W_MW2, MD, D, (size_t)MD * D, (size_t)MD * D);

    for (int i = 0; i < 2; i++) {
        // S = leaky(ctx @ qm^T)
        hgemm<0><<<dim3(2, 1, Bb), 256, SMEM_BYTES>>>(
            pctx16, pqm, nullptr, pS, nullptr, nullptr, nullptr,
            D, NQ, (size_t)NC * D, (size_t)NQ * D, (size_t)NC * NQ);
        normsoftmax_kernel<<<Bb, 256, SMS_BYTES>>>(pS, psm, pattn16, nullptr);
        // d16 = (q - attn@ctx)^2
        hgemm<1><<<dim3(8, 2, Bb), 256, SMEM_BYTES>>>(
            pattn16, pctxT, nullptr, pd16, query, nullptr, nullptr,
            NC, D, (size_t)NQ * NC, (size_t)NC * D, (size_t)NQ * D);
        // common = d16 @ cw_W + b
        hgemm<3><<<dim3(2, 256, 1), 256, SMEM_BYTES>>>(
            pd16, pw16 + W_CW + (size_t)i * D * AD, cw_b + (size_t)i * AD, pcom,
            nullptr, nullptr, nullptr, D, AD, 0, 0, 0);
        l2norm256_kernel<<<Bb * NQ, 256>>>(pcom, pcom16);
        // smooth branch
        hgemm<4><<<dim3(1, 256, 1), 256, SMEM_BYTES>>>(
            pcom16, pw16 + W_SW1 + (size_t)i * AD * HD, sw_b1 + (size_t)i * HD, psh16,
            nullptr, nullptr, nullptr, AD, HD, 0, 0, 0);
        sw_reduce_kernel<<<Bb * NQ / 8, 256>>>(psh16, sw_W2 + (size_t)i * HD, sw_b2 + i, psm);
        // matrix branch
        hgemm<4><<<dim3(4, 256, 1), 256, SMEM_BYTES>>>(
            pcom16, pw16 + W_MW1 + (size_t)i * AD * MD, mw_b1 + (size_t)i * MD, ph16,
            nullptr, nullptr, nullptr, AD, MD, 0, 0, 0);
        hgemm<5><<<dim3(8, 256, 1), 256, SMEM_BYTES>>>(
            ph16, pw16 + W_MW2 + (size_t)i * MD * D, mw_b2 + (size_t)i * D, nullptr,
            query, pmat, pqm, MD, D, 0, 0, 0);
    }

    // final scan -> d_out
    hgemm<0><<<dim3(2, 1, Bb), 256, SMEM_BYTES>>>(
        pctx16, pqm, nullptr, pS, nullptr, nullptr, nullptr,
        D, NQ, (size_t)NC * D, (size_t)NQ * D, (size_t)NC * NQ);
    normsoftmax_kernel<<<Bb, 256, SMS_BYTES>>>(pS, psm, pattn16, out_attn);
    hgemm<2><<<dim3(8, 2, Bb), 256, SMEM_BYTES>>>(
        pattn16, pctxT, nullptr, out_wc, nullptr, nullptr, nullptr,
        NC, D, (size_t)NQ * NC, (size_t)NC * D, (size_t)NQ * D);

    cudaMemcpyAsync(out_q, query, (size_t)Bb * NQ * D * sizeof(float),
                    cudaMemcpyDeviceToDevice, 0);
}

// round 9
// speedup vs baseline: 2.0178x; 1.0129x over previous
#include <cuda_runtime.h>
#include <cuda_fp16.h>
#include <stdint.h>
#include <math.h>

// Problem constants
#define Bb 128
#define NQ 256
#define NC 128
#define D  1024
#define AD 256
#define HD 128
#define MD 512
#define W1N 640   // MD + HD fused N

// packed transposed weight offsets (halves)
#define W_CW  0
#define W_W1  (W_CW + 2 * AD * D)
#define W_W2  (W_W1 + 2 * W1N * AD)
#define W_TOT (W_W2 + 2 * D * MD)

// ---------------- scratch (device globals) ----------------
__device__ float  g_S[Bb * NC * NQ];
__device__ float  g_smooth[Bb * NQ];
__device__ float  g_common[Bb * NQ * AD];
__device__ float  g_pb[2 * W1N];
__device__ __half g_mat16[Bb * NQ * D];
__device__ __half g_q16[Bb * NQ * D];
__device__ __half g_qm16[Bb * NQ * D];
__device__ __half g_ctx16[Bb * NC * D];    // [b][c][d]
__device__ __half g_ctxT16[Bb * D * NC];   // [b][d][c]
__device__ __half g_attn16[Bb * NQ * NC];
__device__ __half g_d16[Bb * NQ * D];
__device__ __half g_com16[Bb * NQ * AD];
__device__ __half g_hs16[Bb * NQ * W1N];   // fused mw1|sw1 hidden
__device__ __half g_w16[W_TOT];

// ---------------- utils ----------------
__device__ __forceinline__ float warp_sum(float v) {
#pragma unroll
    for (int o = 16; o > 0; o >>= 1) v += __shfl_xor_sync(0xffffffffu, v, o);
    return v;
}

__device__ __forceinline__ uint32_t smem_u32(const void* p) {
    uint32_t a;
    asm("{ .reg .u64 t; cvta.to.shared.u64 t, %1; cvt.u32.u64 %0, t; }" : "=r"(a) : "l"(p));
    return a;
}

__device__ __forceinline__ void cpa16(uint32_t dst, const void* src) {
    asm volatile("cp.async.cg.shared.global [%0], [%1], 16;" :: "r"(dst), "l"(src));
}
#define CPA_COMMIT() asm volatile("cp.async.commit_group;" ::: "memory")
#define CPA_WAIT1()  asm volatile("cp.async.wait_group 1;" ::: "memory")
#define CPA_WAIT0()  asm volatile("cp.async.wait_group 0;" ::: "memory")

__device__ __forceinline__ void ldm4(uint32_t* r, uint32_t a) {
    asm volatile("ldmatrix.sync.aligned.m8n8.x4.shared.b16 {%0,%1,%2,%3}, [%4];"
        : "=r"(r[0]), "=r"(r[1]), "=r"(r[2]), "=r"(r[3]) : "r"(a));
}

__device__ __forceinline__ void mma16(float* c, const uint32_t* a, const uint32_t* b) {
    asm volatile(
        "mma.sync.aligned.m16n8k16.row.col.f32.f16.f16.f32 "
        "{%0,%1,%2,%3},{%4,%5,%6,%7},{%8,%9},{%0,%1,%2,%3};"
        : "+f"(c[0]), "+f"(c[1]), "+f"(c[2]), "+f"(c[3])
        : "r"(a[0]), "r"(a[1]), "r"(a[2]), "r"(a[3]), "r"(b[0]), "r"(b[1]));
}

#define STAGE_BYTES 32768
#define SMEM_BYTES  (3 * STAGE_BYTES)

// ---------------- pipelined fp16 GEMM: 3-stage cp.async ring ----------------
// Tile 128(M) x 128(N), K chunks of 64 halves, 2 CTA/SM.
// EPI: 0 leaky->f32 | 1 (q16-v)^2->half | 2 plain f32 | 3 +bias f32
//      4 tanh(v+bias)->half | 5 matrix16 update + qm16
template<int EPI>
__global__ void __launch_bounds__(256, 2) hgemm(
    const __half* __restrict__ A, const __half* __restrict__ Bw,
    const float* __restrict__ bias, void* __restrict__ Cout,
    const __half* __restrict__ q16, __half* __restrict__ mat16,
    __half* __restrict__ qm16,
    int K, int lda, int ldc, size_t sA, size_t sB, size_t sC)
{
    extern __shared__ __half smemh[];
    const uint32_t sbase = smem_u32(smemh);

    const int tid = threadIdx.x;
    const int lane = tid & 31, warp = tid >> 5;
    const int wm = (warp & 3) * 32, wn = (warp >> 2) * 64;
    const int z = blockIdx.z;
    const int m0 = blockIdx.y * 128, n0 = blockIdx.x * 128;

    const __half* Ab = A + (size_t)z * sA;
    const __half* Bp = Bw + (size_t)z * sB;

    const int ar = tid & 127, acb = (tid >> 7) * 4;
    const int NCH = K >> 6;

    float acc[2][8][4];
#pragma unroll
    for (int i = 0; i < 2; i++)
#pragma unroll
        for (int j = 0; j < 8; j++)
#pragma unroll
            for (int r = 0; r < 4; r++) acc[i][j][r] = 0.0f;

    auto load_chunk = [&](int stage, int ch) {
        const uint32_t Abase = sbase + stage * STAGE_BYTES;
        const uint32_t Bbase = Abase + 16384;
        const __half* ga = Ab + (size_t)(m0 + ar) * lda + ch * 64 + acb * 8;
        const __half* gb = Bp + (size_t)(n0 + ar) * K + ch * 64 + acb * 8;
#pragma unroll
        for (int j = 0; j < 4; j++) {
            int c = acb + j;
            uint32_t sw = ((uint32_t)(c ^ (ar & 7))) << 4;
            cpa16(Abase + ar * 128 + sw, ga + j * 8);
            cpa16(Bbase + ar * 128 + sw, gb + j * 8);
        }
    };

    auto compute = [&](int stage) {
        const uint32_t Abase = sbase + stage * STAGE_BYTES;
        const uint32_t Bbase = Abase + 16384;
#pragma unroll
        for (int s16 = 0; s16 < 4; s16++) {
            uint32_t a[2][4];
#pragma unroll
            for (int mi = 0; mi < 2; mi++) {
                int row = wm + mi * 16 + (lane & 15);
                int c = s16 * 2 + (lane >> 4);
                ldm4(a[mi], Abase + row * 128 + (((uint32_t)(c ^ (row & 7))) << 4));
            }
            uint32_t bf[4][4];
#pragma unroll
            for (int nb = 0; nb < 4; nb++) {
                int row = wn + nb * 16 + (lane & 15);
                int c = s16 * 2 + (lane >> 4);
                ldm4(bf[nb], Bbase + row * 128 + (((uint32_t)(c ^ (row & 7))) << 4));
            }
#pragma unroll
            for (int mi = 0; mi < 2; mi++)
#pragma unroll
                for (int nb = 0; nb < 4; nb++) {
                    uint32_t b0[2] = {bf[nb][0], bf[nb][2]};
                    uint32_t b1[2] = {bf[nb][1], bf[nb][3]};
                    mma16(acc[mi][2 * nb], a[mi], b0);
                    mma16(acc[mi][2 * nb + 1], a[mi], b1);
                }
        }
    };

    load_chunk(0, 0);
    CPA_COMMIT();
    if (NCH > 1) { load_chunk(1, 1); CPA_COMMIT(); }

    for (int i = 0; i < NCH; i++) {
        if (i + 2 < NCH) { CPA_WAIT1(); } else { CPA_WAIT0(); }
        __syncthreads();
        if (i + 2 < NCH) {
            load_chunk((i + 2) % 3, i + 2);
            CPA_COMMIT();
        }
        compute(i % 3);
    }

    // ---------------- epilogue (vectorized) ----------------
    const int g = lane >> 2, tg = lane & 3;
#pragma unroll
    for (int mi = 0; mi < 2; mi++) {
#pragma unroll
        for (int ni = 0; ni < 8; ni++) {
            int n = n0 + wn + ni * 8 + 2 * tg;
#pragma unroll
            for (int hh = 0; hh < 2; hh++) {
                int m = m0 + wm + mi * 16 + g + hh * 8;
                size_t o = (size_t)z * sC + (size_t)m * ldc + n;
                float v0 = acc[mi][ni][hh * 2 + 0];
                float v1 = acc[mi][ni][hh * 2 + 1];
                if (EPI == 0) {
                    float2 w;
                    w.x = (v0 >= 0.0f) ? v0 : 0.1f * v0;
                    w.y = (v1 >= 0.0f) ? v1 : 0.1f * v1;
                    *(float2*)((float*)Cout + o) = w;
                } else if (EPI == 1) {
                    __half2 q2 = *(const __half2*)(q16 + o);
                    float t0 = __half2float(__low2half(q2)) - v0;
                    float t1 = __half2float(__high2half(q2)) - v1;
                    *(__half2*)((__half*)Cout + o) = __floats2half2_rn(t0 * t0, t1 * t1);
                } else if (EPI == 2) {
                    float2 w = {v0, v1};
                    *(float2*)((float*)Cout + o) = w;
                } else if (EPI == 3) {
                    float2 w = {v0 + __ldg(bias + n), v1 + __ldg(bias + n + 1)};
                    *(float2*)((float*)Cout + o) = w;
                } else if (EPI == 4) {
                    *(__half2*)((__half*)Cout + o) =
                        __floats2half2_rn(tanhf(v0 + __ldg(bias + n)),
                                          tanhf(v1 + __ldg(bias + n + 1)));
                } else {
                    __half2 old2 = *(__half2*)(mat16 + o);
                    __half2 q2 = *(const __half2*)(q16 + o);
                    float n0v = fminf(1.0f, fmaxf(-1.0f,
                        tanhf(v0 + __ldg(bias + n)) + __half2float(__low2half(old2))));
                    float n1v = fminf(1.0f, fmaxf(-1.0f,
                        tanhf(v1 + __ldg(bias + n + 1)) + __half2float(__high2half(old2))));
                    *(__half2*)(mat16 + o) = __floats2half2_rn(n0v, n1v);
                    *(__half2*)(qm16 + o) = __floats2half2_rn(
                        __half2float(__low2half(q2)) * n0v,
                        __half2float(__high2half(q2)) * n1v);
                }
            }
        }
    }
}

// ---------------- fused rownorm + softmax (one CTA per batch) ----------------
#define SMS_STRIDE 257
#define SMS_BYTES  ((NC * SMS_STRIDE + NC) * 4)
__global__ void __launch_bounds__(256) normsoftmax_kernel(
    const float* __restrict__ S, const float* __restrict__ smooth,
    __half* __restrict__ a16, float* __restrict__ a32)
{
    extern __shared__ float sm[];
    float* sinv = sm + NC * SMS_STRIDE;
    const int b = blockIdx.x;
    const int tid = threadIdx.x;
    const int warp = tid >> 5, lane = tid & 31;

    const float4* Sb = (const float4*)(S + (size_t)b * NC * NQ);
    for (int idx = tid; idx < NC * NQ / 4; idx += 256) {
        int c = idx >> 6;
        int q4 = idx & 63;
        float4 v = Sb[idx];
        float* p = sm + c * SMS_STRIDE + q4 * 4;
        p[0] = v.x; p[1] = v.y; p[2] = v.z; p[3] = v.w;
    }
    __syncthreads();

#pragma unroll
    for (int r = 0; r < 16; r++) {
        int c = warp * 16 + r;
        const float* p = sm + c * SMS_STRIDE;
        float s = 0.0f;
#pragma unroll
        for (int j = 0; j < 8; j++) {
            float x = p[lane + 32 * j];
            s += x * x;
        }
        s = warp_sum(s);
        if (lane == 0) sinv[c] = 1.0f / (sqrtf(s) + 1e-8f);
    }
    __syncthreads();

    for (int qi = warp; qi < NQ; qi += 8) {
        float sf = smooth[b * NQ + qi];
        float v0 = sm[(lane)      * SMS_STRIDE + qi] * sinv[lane]      * sf;
        float v1 = sm[(lane + 32) * SMS_STRIDE + qi] * sinv[lane + 32] * sf;
        float v2 = sm[(lane + 64) * SMS_STRIDE + qi] * sinv[lane + 64] * sf;
        float v3 = sm[(lane + 96) * SMS_STRIDE + qi] * sinv[lane + 96] * sf;
        float mx = fmaxf(fmaxf(v0, v1), fmaxf(v2, v3));
#pragma unroll
        for (int o = 16; o > 0; o >>= 1) mx = fmaxf(mx, __shfl_xor_sync(0xffffffffu, mx, o));
        float e0 = expf(v0 - mx), e1 = expf(v1 - mx), e2 = expf(v2 - mx), e3 = expf(v3 - mx);
        float s = warp_sum(e0 + e1 + e2 + e3);
        float inv = 1.0f / s;
        size_t base = ((size_t)b * NQ + qi) * NC;
        a16[base + lane]      = __float2half_rn(e0 * inv);
        a16[base + lane + 32] = __float2half_rn(e1 * inv);
        a16[base + lane + 64] = __float2half_rn(e2 * inv);
        a16[base + lane + 96] = __float2half_rn(e3 * inv);
        if (a32) {
            a32[base + lane]      = e0 * inv;
            a32[base + lane + 32] = e1 * inv;
            a32[base + lane + 64] = e2 * inv;
            a32[base + lane + 96] = e3 * inv;
        }
    }
}

// ---------------- generic 32x32 tile transpose body ----------------
__device__ __forceinline__ void tr_tile(const float* s, __half* d, int R, int C,
                                        int bx, int by) {
    __shared__ float t[32][33];
    int r0 = by * 32, c0 = bx * 32;
    for (int j = threadIdx.y; j < 32; j += 8)
        t[j][threadIdx.x] = s[(size_t)(r0 + j) * C + c0 + threadIdx.x];
    __syncthreads();
    for (int j = threadIdx.y; j < 32; j += 8)
        d[(size_t)(c0 + j) * R + r0 + threadIdx.x] = __float2half_rn(t[threadIdx.x][j]);
}

// batched ctx transpose: [c][d] -> [d][c] fp16
__global__ void transpose_ctx(const float* __restrict__ ctx, __half* __restrict__ dst) {
    const float* s = ctx + (size_t)blockIdx.z * NC * D;
    __half* d = dst + (size_t)blockIdx.z * NC * D;
    tr_tile(s, d, NC, D, blockIdx.x, blockIdx.y);
}

// all weight transposes in one launch (flattened grid of 1856 blocks)
__global__ void transpose_weights(const float* __restrict__ cw, const float* __restrict__ sw1,
                                  const float* __restrict__ mw1, const float* __restrict__ mw2,
                                  __half* __restrict__ w16) {
    int blk = blockIdx.x;
    const float* src; __half* dst; int R, C;
    if (blk < 512) {               // cw: [D][AD] -> [AD][D]
        int l = blk >> 8; blk &= 255;
        src = cw + (size_t)l * D * AD; dst = w16 + W_CW + (size_t)l * AD * D;
        R = D; C = AD;
    } else if (blk < 576) {        // sw1: [AD][HD] -> [HD][AD] at W1 rows 512+
        blk -= 512; int l = blk >> 5; blk &= 31;
        src = sw1 + (size_t)l * AD * HD; dst = w16 + W_W1 + (size_t)l * W1N * AD + 512 * AD;
        R = AD; C = HD;
    } else if (blk < 832) {        // mw1: [AD][MD] -> [MD][AD] at W1 rows 0-511
        blk -= 576; int l = blk >> 7; blk &= 127;
        src = mw1 + (size_t)l * AD * MD; dst = w16 + W_W1 + (size_t)l * W1N * AD;
        R = AD; C = MD;
    } else {                       // mw2: [MD][D] -> [D][MD]
        blk -= 832; int l = blk >> 9; blk &= 511;
        src = mw2 + (size_t)l * MD * D; dst = w16 + W_W2 + (size_t)l * D * MD;
        R = MD; C = D;
    }
    int bx = blk % (C / 32), by = blk / (C / 32);
    tr_tile(src, dst, R, C, bx, by);
}

// pack fused W1 bias: [l][640] = concat(mw_b1[l][512], sw_b1[l][128])
__global__ void pack_bias(const float* __restrict__ mw_b1, const float* __restrict__ sw_b1,
                          float* __restrict__ pb) {
    int i = blockIdx.x * blockDim.x + threadIdx.x;
    if (i < 2 * W1N) {
        int l = i / W1N, n = i % W1N;
        pb[i] = (n < MD) ? mw_b1[l * MD + n] : sw_b1[l * HD + n - MD];
    }
}

// ---------------- elementwise kernels ----------------
__global__ void init_kernel(const float* __restrict__ query,
                            __half* __restrict__ mat16, float* __restrict__ smooth,
                            __half* __restrict__ q16, __half* __restrict__ qm16) {
    size_t i = ((size_t)blockIdx.x * blockDim.x + threadIdx.x) * 4;
    if (i < (size_t)Bb * NQ * D) {
        float4 q = *(const float4*)(query + i);
        __half2 h0 = __floats2half2_rn(q.x, q.y);
        __half2 h1 = __floats2half2_rn(q.z, q.w);
        __half2 one2 = __floats2half2_rn(1.0f, 1.0f);
        *(__half2*)(q16 + i)      = h0;
        *(__half2*)(q16 + i + 2)  = h1;
        *(__half2*)(qm16 + i)     = h0;
        *(__half2*)(qm16 + i + 2) = h1;
        *(__half2*)(mat16 + i)     = one2;
        *(__half2*)(mat16 + i + 2) = one2;
    }
    if (i < (size_t)Bb * NQ * 4) smooth[i / 4] = 10.0f;
}

__global__ void convert_kernel(const float* __restrict__ src, __half* __restrict__ dst, int n) {
    int i = (blockIdx.x * blockDim.x + threadIdx.x) * 4;
    if (i < n) {
        float4 v = *(const float4*)(src + i);
        *(__half2*)(dst + i)     = __floats2half2_rn(v.x, v.y);
        *(__half2*)(dst + i + 2) = __floats2half2_rn(v.z, v.w);
    }
}

__global__ void l2norm256_kernel(const float* __restrict__ X, __half* __restrict__ Y) {
    const float* p = X + (size_t)blockIdx.x * AD;
    float v = p[threadIdx.x];
    float s = warp_sum(v * v);
    __shared__ float red[8];
    if ((threadIdx.x & 31) == 0) red[threadIdx.x >> 5] = s;
    __syncthreads();
    float t = red[0] + red[1] + red[2] + red[3] + red[4] + red[5] + red[6] + red[7];
    Y[(size_t)blockIdx.x * AD + threadIdx.x] = __float2half_rn(v / (sqrtf(t) + 1e-8f));
}

__global__ void sw_reduce_kernel(const __half* __restrict__ hs, const float* __restrict__ w2,
                                 const float* __restrict__ b2, float* __restrict__ smooth)
{
    int row = blockIdx.x * 8 + (threadIdx.x >> 5);
    int lane = threadIdx.x & 31;
    const __half* r = hs + (size_t)row * W1N + MD;
    float s = __half2float(r[lane]) * w2[lane]
            + __half2float(r[lane + 32]) * w2[lane + 32]
            + __half2float(r[lane + 64]) * w2[lane + 64]
            + __half2float(r[lane + 96]) * w2[lane + 96];
    s = warp_sum(s);
    if (lane == 0) smooth[row] = fmaxf(0.0f, s + b2[0] + smooth[row]);
}

// ---------------- orchestration ----------------
extern "C" void kernel_launch(void* const* d_in, const int* in_sizes, int n_in,
                              void* d_out, int out_size)
{
    const float* query = (const float*)d_in[0];
    const float* ctx   = (const float*)d_in[1];
    const float* cw_W  = (const float*)d_in[2];
    const float* cw_b  = (const float*)d_in[3];
    const float* sw_W1 = (const float*)d_in[4];
    const float* sw_b1 = (const float*)d_in[5];
    const float* sw_W2 = (const float*)d_in[6];
    const float* sw_b2 = (const float*)d_in[7];
    const float* mw_W1 = (const float*)d_in[8];
    const float* mw_b1 = (const float*)d_in[9];
    const float* mw_W2 = (const float*)d_in[10];
    const float* mw_b2 = (const float*)d_in[11];

    float* out      = (float*)d_out;
    float* out_q    = out;
    float* out_wc   = out + (size_t)Bb * NQ * D;
    float* out_attn = out + 2 * (size_t)Bb * NQ * D;

    float *pS, *psm, *pcom, *ppb;
    __half *pmat, *pq16, *pqm, *pctx16, *pctxT, *pattn16, *pd16, *pcom16, *phs16, *pw16;
    cudaGetSymbolAddress((void**)&pS,      g_S);
    cudaGetSymbolAddress((void**)&psm,     g_smooth);
    cudaGetSymbolAddress((void**)&pcom,    g_common);
    cudaGetSymbolAddress((void**)&ppb,     g_pb);
    cudaGetSymbolAddress((void**)&pmat,    g_mat16);
    cudaGetSymbolAddress((void**)&pq16,    g_q16);
    cudaGetSymbolAddress((void**)&pqm,     g_qm16);
    cudaGetSymbolAddress((void**)&pctx16,  g_ctx16);
    cudaGetSymbolAddress((void**)&pctxT,   g_ctxT16);
    cudaGetSymbolAddress((void**)&pattn16, g_attn16);
    cudaGetSymbolAddress((void**)&pd16,    g_d16);
    cudaGetSymbolAddress((void**)&pcom16,  g_com16);
    cudaGetSymbolAddress((void**)&phs16,   g_hs16);
    cudaGetSymbolAddress((void**)&pw16,    g_w16);

    cudaFuncSetAttribute(hgemm<0>, cudaFuncAttributeMaxDynamicSharedMemorySize, SMEM_BYTES);
    cudaFuncSetAttribute(hgemm<1>, cudaFuncAttributeMaxDynamicSharedMemorySize, SMEM_BYTES);
    cudaFuncSetAttribute(hgemm<2>, cudaFuncAttributeMaxDynamicSharedMemorySize, SMEM_BYTES);
    cudaFuncSetAttribute(hgemm<3>, cudaFuncAttributeMaxDynamicSharedMemorySize, SMEM_BYTES);
    cudaFuncSetAttribute(hgemm<4>, cudaFuncAttributeMaxDynamicSharedMemorySize, SMEM_BYTES);
    cudaFuncSetAttribute(hgemm<5>, cudaFuncAttributeMaxDynamicSharedMemorySize, SMEM_BYTES);
    cudaFuncSetAttribute(normsoftmax_kernel, cudaFuncAttributeMaxDynamicSharedMemorySize, SMS_BYTES);

    // prep: launches 0-4 (so ncu -s 5 captures the S-GEMM)
    init_kernel<<<(Bb * NQ * D / 4 + 255) / 256, 256>>>(query, pmat, psm, pq16, pqm);
    convert_kernel<<<(Bb * NC * D / 4 + 255) / 256, 256>>>(ctx, pctx16, Bb * NC * D);
    transpose_ctx<<<dim3(D / 32, NC / 32, Bb), dim3(32, 8)>>>(ctx, pctxT);
    transpose_weights<<<1856, dim3(32, 8)>>>(cw_W, sw_W1, mw_W1, mw_W2, pw16);
    pack_bias<<<(2 * W1N + 255) / 256, 256>>>(mw_b1, sw_b1, ppb);

    for (int i = 0; i < 2; i++) {
        // S = leaky(ctx @ qm^T)
        hgemm<0><<<dim3(2, 1, Bb), 256, SMEM_BYTES>>>(
            pctx16, pqm, nullptr, pS, nullptr, nullptr, nullptr,
            D, D, NQ, (size_t)NC * D, (size_t)NQ * D, (size_t)NC * NQ);
        normsoftmax_kernel<<<Bb, 256, SMS_BYTES>>>(pS, psm, pattn16, nullptr);
        // d16 = (q - attn@ctx)^2
        hgemm<1><<<dim3(8, 2, Bb), 256, SMEM_BYTES>>>(
            pattn16, pctxT, nullptr, pd16, pq16, nullptr, nullptr,
            NC, NC, D, (size_t)NQ * NC, (size_t)NC * D, (size_t)NQ * D);
        // common = d16 @ cw_W + b (f32)
        hgemm<3><<<dim3(2, 256, 1), 256, SMEM_BYTES>>>(
            pd16, pw16 + W_CW + (size_t)i * AD * D, cw_b + (size_t)i * AD, pcom,
            nullptr, nullptr, nullptr, D, D, AD, 0, 0, 0);
        l2norm256_kernel<<<Bb * NQ, 256>>>(pcom, pcom16);
        // fused W1: [h | sh] = tanh(com16 @ [mw1|sw1] + [b])
        hgemm<4><<<dim3(5, 256, 1), 256, SMEM_BYTES>>>(
            pcom16, pw16 + W_W1 + (size_t)i * W1N * AD, ppb + (size_t)i * W1N, phs16,
            nullptr, nullptr, nullptr, AD, AD, W1N, 0, 0, 0);
        sw_reduce_kernel<<<Bb * NQ / 8, 256>>>(phs16, sw_W2 + (size_t)i * HD, sw_b2 + i, psm);
        // matrix update: mat16/qm16 from h @ mw2
        hgemm<5><<<dim3(8, 256, 1), 256, SMEM_BYTES>>>(
            phs16, pw16 + W_W2 + (size_t)i * D * MD, mw_b2 + (size_t)i * D, nullptr,
            pq16, pmat, pqm, MD, W1N, D, 0, 0, 0);
    }

    // final scan -> d_out
    hgemm<0><<<dim3(2, 1, Bb), 256, SMEM_BYTES>>>(
        pctx16, pqm, nullptr, pS, nullptr, nullptr, nullptr,
        D, D, NQ, (size_t)NC * D, (size_t)NQ * D, (size_t)NC * NQ);
    normsoftmax_kernel<<<Bb, 256, SMS_BYTES>>>(pS, psm, pattn16, out_attn);
    hgemm<2><<<dim3(8, 2, Bb), 256, SMEM_BYTES>>>(
        pattn16, pctxT, nullptr, out_wc, nullptr, nullptr, nullptr,
        NC, NC, D, (size_t)NQ * NC, (size_t)NC * D, (size_t)NQ * D);

    cudaMemcpyAsync(out_q, query, (size_t)Bb * NQ * D * sizeof(float),
                    cudaMemcpyDeviceToDevice, 0);
}

// round 10
// speedup vs baseline: 2.1991x; 1.0898x over previous
#include <cuda_runtime.h>
#include <cuda_fp16.h>
#include <stdint.h>
#include <math.h>

// Problem constants
#define Bb 128
#define NQ 256
#define NC 128
#define D  1024
#define AD 256
#define HD 128
#define MD 512
#define W1N 640   // MD + HD fused N

// packed transposed weight offsets (halves)
#define W_CW  0
#define W_W1  (W_CW + 2 * AD * D)
#define W_W2  (W_W1 + 2 * W1N * AD)
#define W_TOT (W_W2 + 2 * D * MD)

// ---------------- scratch (device globals) ----------------
__device__ float  g_smooth[Bb * NQ];
__device__ float  g_common[Bb * NQ * AD];
__device__ float  g_pb[2 * W1N];
__device__ __half g_mat16[Bb * NQ * D];
__device__ __half g_q16[Bb * NQ * D];
__device__ __half g_qm16[Bb * NQ * D];
__device__ __half g_ctx16[Bb * NC * D];    // [b][c][d]
__device__ __half g_ctxT16[Bb * D * NC];   // [b][d][c]
__device__ __half g_attn16[Bb * NQ * NC];
__device__ __half g_d16[Bb * NQ * D];
__device__ __half g_com16[Bb * NQ * AD];
__device__ __half g_hs16[Bb * NQ * W1N];   // fused mw1|sw1 hidden
__device__ __half g_w16[W_TOT];

// ---------------- utils ----------------
__device__ __forceinline__ float warp_sum(float v) {
#pragma unroll
    for (int o = 16; o > 0; o >>= 1) v += __shfl_xor_sync(0xffffffffu, v, o);
    return v;
}

__device__ __forceinline__ uint32_t smem_u32(const void* p) {
    uint32_t a;
    asm("{ .reg .u64 t; cvta.to.shared.u64 t, %1; cvt.u32.u64 %0, t; }" : "=r"(a) : "l"(p));
    return a;
}

__device__ __forceinline__ void cpa16(uint32_t dst, const void* src) {
    asm volatile("cp.async.cg.shared.global [%0], [%1], 16;" :: "r"(dst), "l"(src));
}
#define CPA_COMMIT() asm volatile("cp.async.commit_group;" ::: "memory")
#define CPA_WAIT1()  asm volatile("cp.async.wait_group 1;" ::: "memory")
#define CPA_WAIT0()  asm volatile("cp.async.wait_group 0;" ::: "memory")

__device__ __forceinline__ void ldm4(uint32_t* r, uint32_t a) {
    asm volatile("ldmatrix.sync.aligned.m8n8.x4.shared.b16 {%0,%1,%2,%3}, [%4];"
        : "=r"(r[0]), "=r"(r[1]), "=r"(r[2]), "=r"(r[3]) : "r"(a));
}

__device__ __forceinline__ void mma16(float* c, const uint32_t* a, const uint32_t* b) {
    asm volatile(
        "mma.sync.aligned.m16n8k16.row.col.f32.f16.f16.f32 "
        "{%0,%1,%2,%3},{%4,%5,%6,%7},{%8,%9},{%0,%1,%2,%3};"
        : "+f"(c[0]), "+f"(c[1]), "+f"(c[2]), "+f"(c[3])
        : "r"(a[0]), "r"(a[1]), "r"(a[2]), "r"(a[3]), "r"(b[0]), "r"(b[1]));
}

#define STAGE_BYTES 32768
#define SMEM_BYTES  (3 * STAGE_BYTES)

// ---------------- pipelined fp16 GEMM: 3-stage cp.async ring ----------------
// Tile 128(M) x 128(N), K chunks of 64 halves, 2 CTA/SM.
// EPI: 1 (q16-v)^2->half | 2 plain f32 | 3 +bias f32
//      4 tanh(v+bias)->half | 5 matrix16 update + qm16
template<int EPI>
__global__ void __launch_bounds__(256, 2) hgemm(
    const __half* __restrict__ A, const __half* __restrict__ Bw,
    const float* __restrict__ bias, void* __restrict__ Cout,
    const __half* __restrict__ q16, __half* __restrict__ mat16,
    __half* __restrict__ qm16,
    int K, int lda, int ldc, size_t sA, size_t sB, size_t sC)
{
    extern __shared__ __half smemh[];
    const uint32_t sbase = smem_u32(smemh);

    const int tid = threadIdx.x;
    const int lane = tid & 31, warp = tid >> 5;
    const int wm = (warp & 3) * 32, wn = (warp >> 2) * 64;
    const int z = blockIdx.z;
    const int m0 = blockIdx.y * 128, n0 = blockIdx.x * 128;

    const __half* Ab = A + (size_t)z * sA;
    const __half* Bp = Bw + (size_t)z * sB;

    const int ar = tid & 127, acb = (tid >> 7) * 4;
    const int NCH = K >> 6;

    float acc[2][8][4];
#pragma unroll
    for (int i = 0; i < 2; i++)
#pragma unroll
        for (int j = 0; j < 8; j++)
#pragma unroll
            for (int r = 0; r < 4; r++) acc[i][j][r] = 0.0f;

    auto load_chunk = [&](int stage, int ch) {
        const uint32_t Abase = sbase + stage * STAGE_BYTES;
        const uint32_t Bbase = Abase + 16384;
        const __half* ga = Ab + (size_t)(m0 + ar) * lda + ch * 64 + acb * 8;
        const __half* gb = Bp + (size_t)(n0 + ar) * K + ch * 64 + acb * 8;
#pragma unroll
        for (int j = 0; j < 4; j++) {
            int c = acb + j;
            uint32_t sw = ((uint32_t)(c ^ (ar & 7))) << 4;
            cpa16(Abase + ar * 128 + sw, ga + j * 8);
            cpa16(Bbase + ar * 128 + sw, gb + j * 8);
        }
    };

    auto compute = [&](int stage) {
        const uint32_t Abase = sbase + stage * STAGE_BYTES;
        const uint32_t Bbase = Abase + 16384;
#pragma unroll
        for (int s16 = 0; s16 < 4; s16++) {
            uint32_t a[2][4];
#pragma unroll
            for (int mi = 0; mi < 2; mi++) {
                int row = wm + mi * 16 + (lane & 15);
                int c = s16 * 2 + (lane >> 4);
                ldm4(a[mi], Abase + row * 128 + (((uint32_t)(c ^ (row & 7))) << 4));
            }
            uint32_t bf[4][4];
#pragma unroll
            for (int nb = 0; nb < 4; nb++) {
                int row = wn + nb * 16 + (lane & 15);
                int c = s16 * 2 + (lane >> 4);
                ldm4(bf[nb], Bbase + row * 128 + (((uint32_t)(c ^ (row & 7))) << 4));
            }
#pragma unroll
            for (int mi = 0; mi < 2; mi++)
#pragma unroll
                for (int nb = 0; nb < 4; nb++) {
                    uint32_t b0[2] = {bf[nb][0], bf[nb][2]};
                    uint32_t b1[2] = {bf[nb][1], bf[nb][3]};
                    mma16(acc[mi][2 * nb], a[mi], b0);
                    mma16(acc[mi][2 * nb + 1], a[mi], b1);
                }
        }
    };

    load_chunk(0, 0);
    CPA_COMMIT();
    if (NCH > 1) { load_chunk(1, 1); CPA_COMMIT(); }

    for (int i = 0; i < NCH; i++) {
        if (i + 2 < NCH) { CPA_WAIT1(); } else { CPA_WAIT0(); }
        __syncthreads();
        if (i + 2 < NCH) {
            load_chunk((i + 2) % 3, i + 2);
            CPA_COMMIT();
        }
        compute(i % 3);
    }

    // ---------------- epilogue (vectorized) ----------------
    const int g = lane >> 2, tg = lane & 3;
#pragma unroll
    for (int mi = 0; mi < 2; mi++) {
#pragma unroll
        for (int ni = 0; ni < 8; ni++) {
            int n = n0 + wn + ni * 8 + 2 * tg;
#pragma unroll
            for (int hh = 0; hh < 2; hh++) {
                int m = m0 + wm + mi * 16 + g + hh * 8;
                size_t o = (size_t)z * sC + (size_t)m * ldc + n;
                float v0 = acc[mi][ni][hh * 2 + 0];
                float v1 = acc[mi][ni][hh * 2 + 1];
                if (EPI == 1) {
                    __half2 q2 = *(const __half2*)(q16 + o);
                    float t0 = __half2float(__low2half(q2)) - v0;
                    float t1 = __half2float(__high2half(q2)) - v1;
                    *(__half2*)((__half*)Cout + o) = __floats2half2_rn(t0 * t0, t1 * t1);
                } else if (EPI == 2) {
                    float2 w = {v0, v1};
                    *(float2*)((float*)Cout + o) = w;
                } else if (EPI == 3) {
                    float2 w = {v0 + __ldg(bias + n), v1 + __ldg(bias + n + 1)};
                    *(float2*)((float*)Cout + o) = w;
                } else if (EPI == 4) {
                    *(__half2*)((__half*)Cout + o) =
                        __floats2half2_rn(tanhf(v0 + __ldg(bias + n)),
                                          tanhf(v1 + __ldg(bias + n + 1)));
                } else {
                    __half2 old2 = *(__half2*)(mat16 + o);
                    __half2 q2 = *(const __half2*)(q16 + o);
                    float n0v = fminf(1.0f, fmaxf(-1.0f,
                        tanhf(v0 + __ldg(bias + n)) + __half2float(__low2half(old2))));
                    float n1v = fminf(1.0f, fmaxf(-1.0f,
                        tanhf(v1 + __ldg(bias + n + 1)) + __half2float(__high2half(old2))));
                    *(__half2*)(mat16 + o) = __floats2half2_rn(n0v, n1v);
                    *(__half2*)(qm16 + o) = __floats2half2_rn(
                        __half2float(__low2half(q2)) * n0v,
                        __half2float(__high2half(q2)) * n1v);
                }
            }
        }
    }
}

// ---------------- fused attention scan: S-GEMM + leaky + rownorm + softmax ----
// One CTA per batch. Tile M=NC=128 (rows c), N=NQ=256 (cols q), K=D=1024.
// 512 threads = 16 warps (4M x 4N). 3-stage cp.async ring (48KB/stage), then
// smem f32 buffer [128][257] for norm+softmax. attn16 out (+optional f32 out).
#define AT_STAGE   49152
#define AT_SMSTR   257
#define AT_SMEM    (3 * AT_STAGE)   // 147456 >= softmax region 132096
__global__ void __launch_bounds__(512, 1) attn_fused(
    const __half* __restrict__ ctx16, const __half* __restrict__ qm16,
    const float* __restrict__ smooth,
    __half* __restrict__ a16, float* __restrict__ a32)
{
    extern __shared__ __half smemh[];
    const uint32_t sbase = smem_u32(smemh);
    float* smf = (float*)smemh;                 // softmax buffer (reuses stages)
    float* sinv = smf + NC * AT_SMSTR;

    const int tid = threadIdx.x;
    const int lane = tid & 31, warp = tid >> 5;
    const int wm = (warp & 3) * 32, wn = (warp >> 2) * 64;
    const int b = blockIdx.x;

    const __half* Ab = ctx16 + (size_t)b * NC * D;
    const __half* Bp = qm16 + (size_t)b * NQ * D;

    // loader mappings
    const int arow = tid >> 2, ac0 = (tid & 3) * 2;   // A: 128 rows x 8 chunks
    const int brow = tid >> 1, bc0 = (tid & 1) * 4;   // B: 256 rows x 8 chunks

    float acc[2][8][4];
#pragma unroll
    for (int i = 0; i < 2; i++)
#pragma unroll
        for (int j = 0; j < 8; j++)
#pragma unroll
            for (int r = 0; r < 4; r++) acc[i][j][r] = 0.0f;

    auto load_chunk = [&](int stage, int ch) {
        const uint32_t Abase = sbase + stage * AT_STAGE;
        const uint32_t Bbase = Abase + 16384;
        const __half* ga = Ab + (size_t)arow * D + ch * 64 + ac0 * 8;
#pragma unroll
        for (int j = 0; j < 2; j++) {
            int c = ac0 + j;
            cpa16(Abase + arow * 128 + (((uint32_t)(c ^ (arow & 7))) << 4), ga + j * 8);
        }
        const __half* gb = Bp + (size_t)brow * D + ch * 64 + bc0 * 8;
#pragma unroll
        for (int j = 0; j < 4; j++) {
            int c = bc0 + j;
            cpa16(Bbase + brow * 128 + (((uint32_t)(c ^ (brow & 7))) << 4), gb + j * 8);
        }
    };

    auto compute = [&](int stage) {
        const uint32_t Abase = sbase + stage * AT_STAGE;
        const uint32_t Bbase = Abase + 16384;
#pragma unroll
        for (int s16 = 0; s16 < 4; s16++) {
            uint32_t a[2][4];
#pragma unroll
            for (int mi = 0; mi < 2; mi++) {
                int row = wm + mi * 16 + (lane & 15);
                int c = s16 * 2 + (lane >> 4);
                ldm4(a[mi], Abase + row * 128 + (((uint32_t)(c ^ (row & 7))) << 4));
            }
            uint32_t bf[4][4];
#pragma unroll
            for (int nb = 0; nb < 4; nb++) {
                int row = wn + nb * 16 + (lane & 15);
                int c = s16 * 2 + (lane >> 4);
                ldm4(bf[nb], Bbase + row * 128 + (((uint32_t)(c ^ (row & 7))) << 4));
            }
#pragma unroll
            for (int mi = 0; mi < 2; mi++)
#pragma unroll
                for (int nb = 0; nb < 4; nb++) {
                    uint32_t b0[2] = {bf[nb][0], bf[nb][2]};
                    uint32_t b1[2] = {bf[nb][1], bf[nb][3]};
                    mma16(acc[mi][2 * nb], a[mi], b0);
                    mma16(acc[mi][2 * nb + 1], a[mi], b1);
                }
        }
    };

    const int NCH = D >> 6;   // 16
    load_chunk(0, 0);
    CPA_COMMIT();
    load_chunk(1, 1);
    CPA_COMMIT();
    for (int i = 0; i < NCH; i++) {
        if (i + 2 < NCH) { CPA_WAIT1(); } else { CPA_WAIT0(); }
        __syncthreads();
        if (i + 2 < NCH) {
            load_chunk((i + 2) % 3, i + 2);
            CPA_COMMIT();
        }
        compute(i % 3);
    }

    // ---- leaky -> smem f32 buffer (overwrites stage memory) ----
    __syncthreads();
    const int g = lane >> 2, tg = lane & 3;
#pragma unroll
    for (int mi = 0; mi < 2; mi++) {
#pragma unroll
        for (int ni = 0; ni < 8; ni++) {
            int n = wn + ni * 8 + 2 * tg;
#pragma unroll
            for (int hh = 0; hh < 2; hh++) {
                int m = wm + mi * 16 + g + hh * 8;
                float v0 = acc[mi][ni][hh * 2 + 0];
                float v1 = acc[mi][ni][hh * 2 + 1];
                smf[m * AT_SMSTR + n]     = (v0 >= 0.0f) ? v0 : 0.1f * v0;
                smf[m * AT_SMSTR + n + 1] = (v1 >= 0.0f) ? v1 : 0.1f * v1;
            }
        }
    }
    __syncthreads();

    // ---- row l2norm over q (warp w handles rows w*8 .. w*8+7) ----
#pragma unroll
    for (int r = 0; r < 8; r++) {
        int c = warp * 8 + r;
        const float* p = smf + c * AT_SMSTR;
        float s = 0.0f;
#pragma unroll
        for (int j = 0; j < 8; j++) {
            float x = p[lane + 32 * j];
            s += x * x;
        }
        s = warp_sum(s);
        if (lane == 0) sinv[c] = 1.0f / (sqrtf(s) + 1e-8f);
    }
    __syncthreads();

    // ---- softmax over c per q (warp w: q = w, w+16, ...) ----
    for (int qi = warp; qi < NQ; qi += 16) {
        float sf = smooth[b * NQ + qi];
        float v0 = smf[(lane)      * AT_SMSTR + qi] * sinv[lane]      * sf;
        float v1 = smf[(lane + 32) * AT_SMSTR + qi] * sinv[lane + 32] * sf;
        float v2 = smf[(lane + 64) * AT_SMSTR + qi] * sinv[lane + 64] * sf;
        float v3 = smf[(lane + 96) * AT_SMSTR + qi] * sinv[lane + 96] * sf;
        float mx = fmaxf(fmaxf(v0, v1), fmaxf(v2, v3));
#pragma unroll
        for (int o = 16; o > 0; o >>= 1) mx = fmaxf(mx, __shfl_xor_sync(0xffffffffu, mx, o));
        float e0 = expf(v0 - mx), e1 = expf(v1 - mx), e2 = expf(v2 - mx), e3 = expf(v3 - mx);
        float s = warp_sum(e0 + e1 + e2 + e3);
        float inv = 1.0f / s;
        size_t base = ((size_t)b * NQ + qi) * NC;
        a16[base + lane]      = __float2half_rn(e0 * inv);
        a16[base + lane + 32] = __float2half_rn(e1 * inv);
        a16[base + lane + 64] = __float2half_rn(e2 * inv);
        a16[base + lane + 96] = __float2half_rn(e3 * inv);
        if (a32) {
            a32[base + lane]      = e0 * inv;
            a32[base + lane + 32] = e1 * inv;
            a32[base + lane + 64] = e2 * inv;
            a32[base + lane + 96] = e3 * inv;
        }
    }
}

// ---------------- generic 32x32 tile transpose body ----------------
__device__ __forceinline__ void tr_tile(const float* s, __half* d, int R, int C,
                                        int bx, int by) {
    __shared__ float t[32][33];
    int r0 = by * 32, c0 = bx * 32;
    for (int j = threadIdx.y; j < 32; j += 8)
        t[j][threadIdx.x] = s[(size_t)(r0 + j) * C + c0 + threadIdx.x];
    __syncthreads();
    for (int j = threadIdx.y; j < 32; j += 8)
        d[(size_t)(c0 + j) * R + r0 + threadIdx.x] = __float2half_rn(t[threadIdx.x][j]);
}

__global__ void transpose_ctx(const float* __restrict__ ctx, __half* __restrict__ dst) {
    const float* s = ctx + (size_t)blockIdx.z * NC * D;
    __half* d = dst + (size_t)blockIdx.z * NC * D;
    tr_tile(s, d, NC, D, blockIdx.x, blockIdx.y);
}

__global__ void transpose_weights(const float* __restrict__ cw, const float* __restrict__ sw1,
                                  const float* __restrict__ mw1, const float* __restrict__ mw2,
                                  __half* __restrict__ w16) {
    int blk = blockIdx.x;
    const float* src; __half* dst; int R, C;
    if (blk < 512) {
        int l = blk >> 8; blk &= 255;
        src = cw + (size_t)l * D * AD; dst = w16 + W_CW + (size_t)l * AD * D;
        R = D; C = AD;
    } else if (blk < 576) {
        blk -= 512; int l = blk >> 5; blk &= 31;
        src = sw1 + (size_t)l * AD * HD; dst = w16 + W_W1 + (size_t)l * W1N * AD + 512 * AD;
        R = AD; C = HD;
    } else if (blk < 832) {
        blk -= 576; int l = blk >> 7; blk &= 127;
        src = mw1 + (size_t)l * AD * MD; dst = w16 + W_W1 + (size_t)l * W1N * AD;
        R = AD; C = MD;
    } else {
        blk -= 832; int l = blk >> 9; blk &= 511;
        src = mw2 + (size_t)l * MD * D; dst = w16 + W_W2 + (size_t)l * D * MD;
        R = MD; C = D;
    }
    int bx = blk % (C / 32), by = blk / (C / 32);
    tr_tile(src, dst, R, C, bx, by);
}

__global__ void pack_bias(const float* __restrict__ mw_b1, const float* __restrict__ sw_b1,
                          float* __restrict__ pb) {
    int i = blockIdx.x * blockDim.x + threadIdx.x;
    if (i < 2 * W1N) {
        int l = i / W1N, n = i % W1N;
        pb[i] = (n < MD) ? mw_b1[l * MD + n] : sw_b1[l * HD + n - MD];
    }
}

// ---------------- elementwise kernels ----------------
__global__ void init_kernel(const float* __restrict__ query,
                            __half* __restrict__ mat16, float* __restrict__ smooth,
                            __half* __restrict__ q16, __half* __restrict__ qm16) {
    size_t i = ((size_t)blockIdx.x * blockDim.x + threadIdx.x) * 4;
    if (i < (size_t)Bb * NQ * D) {
        float4 q = *(const float4*)(query + i);
        __half2 h0 = __floats2half2_rn(q.x, q.y);
        __half2 h1 = __floats2half2_rn(q.z, q.w);
        __half2 one2 = __floats2half2_rn(1.0f, 1.0f);
        *(__half2*)(q16 + i)      = h0;
        *(__half2*)(q16 + i + 2)  = h1;
        *(__half2*)(qm16 + i)     = h0;
        *(__half2*)(qm16 + i + 2) = h1;
        *(__half2*)(mat16 + i)     = one2;
        *(__half2*)(mat16 + i + 2) = one2;
    }
    if (i < (size_t)Bb * NQ * 4) smooth[i / 4] = 10.0f;
}

__global__ void convert_kernel(const float* __restrict__ src, __half* __restrict__ dst, int n) {
    int i = (blockIdx.x * blockDim.x + threadIdx.x) * 4;
    if (i < n) {
        float4 v = *(const float4*)(src + i);
        *(__half2*)(dst + i)     = __floats2half2_rn(v.x, v.y);
        *(__half2*)(dst + i + 2) = __floats2half2_rn(v.z, v.w);
    }
}

// l2norm over AD=256: warp per row, 8 rows per CTA
__global__ void l2norm256_kernel(const float* __restrict__ X, __half* __restrict__ Y) {
    int row = blockIdx.x * 8 + (threadIdx.x >> 5);
    int lane = threadIdx.x & 31;
    const float* p = X + (size_t)row * AD;
    float vals[8];
    float s = 0.0f;
#pragma unroll
    for (int j = 0; j < 8; j++) {
        vals[j] = p[lane + 32 * j];
        s += vals[j] * vals[j];
    }
    s = warp_sum(s);
    float inv = 1.0f / (sqrtf(s) + 1e-8f);
    __half* y = Y + (size_t)row * AD;
#pragma unroll
    for (int j = 0; j < 8; j++)
        y[lane + 32 * j] = __float2half_rn(vals[j] * inv);
}

__global__ void sw_reduce_kernel(const __half* __restrict__ hs, const float* __restrict__ w2,
                                 const float* __restrict__ b2, float* __restrict__ smooth)
{
    int row = blockIdx.x * 8 + (threadIdx.x >> 5);
    int lane = threadIdx.x & 31;
    const __half* r = hs + (size_t)row * W1N + MD;
    float s = __half2float(r[lane]) * w2[lane]
            + __half2float(r[lane + 32]) * w2[lane + 32]
            + __half2float(r[lane + 64]) * w2[lane + 64]
            + __half2float(r[lane + 96]) * w2[lane + 96];
    s = warp_sum(s);
    if (lane == 0) smooth[row] = fmaxf(0.0f, s + b2[0] + smooth[row]);
}

// ---------------- orchestration ----------------
extern "C" void kernel_launch(void* const* d_in, const int* in_sizes, int n_in,
                              void* d_out, int out_size)
{
    const float* query = (const float*)d_in[0];
    const float* ctx   = (const float*)d_in[1];
    const float* cw_W  = (const float*)d_in[2];
    const float* cw_b  = (const float*)d_in[3];
    const float* sw_W1 = (const float*)d_in[4];
    const float* sw_b1 = (const float*)d_in[5];
    const float* sw_W2 = (const float*)d_in[6];
    const float* sw_b2 = (const float*)d_in[7];
    const float* mw_W1 = (const float*)d_in[8];
    const float* mw_b1 = (const float*)d_in[9];
    const float* mw_W2 = (const float*)d_in[10];
    const float* mw_b2 = (const float*)d_in[11];

    float* out      = (float*)d_out;
    float* out_q    = out;
    float* out_wc   = out + (size_t)Bb * NQ * D;
    float* out_attn = out + 2 * (size_t)Bb * NQ * D;

    float *psm, *pcom, *ppb;
    __half *pmat, *pq16, *pqm, *pctx16, *pctxT, *pattn16, *pd16, *pcom16, *phs16, *pw16;
    cudaGetSymbolAddress((void**)&psm,     g_smooth);
    cudaGetSymbolAddress((void**)&pcom,    g_common);
    cudaGetSymbolAddress((void**)&ppb,     g_pb);
    cudaGetSymbolAddress((void**)&pmat,    g_mat16);
    cudaGetSymbolAddress((void**)&pq16,    g_q16);
    cudaGetSymbolAddress((void**)&pqm,     g_qm16);
    cudaGetSymbolAddress((void**)&pctx16,  g_ctx16);
    cudaGetSymbolAddress((void**)&pctxT,   g_ctxT16);
    cudaGetSymbolAddress((void**)&pattn16, g_attn16);
    cudaGetSymbolAddress((void**)&pd16,    g_d16);
    cudaGetSymbolAddress((void**)&pcom16,  g_com16);
    cudaGetSymbolAddress((void**)&phs16,   g_hs16);
    cudaGetSymbolAddress((void**)&pw16,    g_w16);

    cudaFuncSetAttribute(hgemm<1>, cudaFuncAttributeMaxDynamicSharedMemorySize, SMEM_BYTES);
    cudaFuncSetAttribute(hgemm<2>, cudaFuncAttributeMaxDynamicSharedMemorySize, SMEM_BYTES);
    cudaFuncSetAttribute(hgemm<3>, cudaFuncAttributeMaxDynamicSharedMemorySize, SMEM_BYTES);
    cudaFuncSetAttribute(hgemm<4>, cudaFuncAttributeMaxDynamicSharedMemorySize, SMEM_BYTES);
    cudaFuncSetAttribute(hgemm<5>, cudaFuncAttributeMaxDynamicSharedMemorySize, SMEM_BYTES);
    cudaFuncSetAttribute(attn_fused, cudaFuncAttributeMaxDynamicSharedMemorySize, AT_SMEM);

    // prep
    init_kernel<<<(Bb * NQ * D / 4 + 255) / 256, 256>>>(query, pmat, psm, pq16, pqm);
    convert_kernel<<<(Bb * NC * D / 4 + 255) / 256, 256>>>(ctx, pctx16, Bb * NC * D);
    transpose_ctx<<<dim3(D / 32, NC / 32, Bb), dim3(32, 8)>>>(ctx, pctxT);
    transpose_weights<<<1856, dim3(32, 8)>>>(cw_W, sw_W1, mw_W1, mw_W2, pw16);
    pack_bias<<<(2 * W1N + 255) / 256, 256>>>(mw_b1, sw_b1, ppb);

    for (int i = 0; i < 2; i++) {
        // fused attention scan -> attn16
        attn_fused<<<Bb, 512, AT_SMEM>>>(pctx16, pqm, psm, pattn16, nullptr);
        // d16 = (q - attn@ctx)^2
        hgemm<1><<<dim3(8, 2, Bb), 256, SMEM_BYTES>>>(
            pattn16, pctxT, nullptr, pd16, pq16, nullptr, nullptr,
            NC, NC, D, (size_t)NQ * NC, (size_t)NC * D, (size_t)NQ * D);
        // common = d16 @ cw_W + b (f32)
        hgemm<3><<<dim3(2, 256, 1), 256, SMEM_BYTES>>>(
            pd16, pw16 + W_CW + (size_t)i * AD * D, cw_b + (size_t)i * AD, pcom,
            nullptr, nullptr, nullptr, D, D, AD, 0, 0, 0);
        l2norm256_kernel<<<Bb * NQ / 8, 256>>>(pcom, pcom16);
        // fused W1: [h | sh] = tanh(com16 @ [mw1|sw1] + [b])
        hgemm<4><<<dim3(5, 256, 1), 256, SMEM_BYTES>>>(
            pcom16, pw16 + W_W1 + (size_t)i * W1N * AD, ppb + (size_t)i * W1N, phs16,
            nullptr, nullptr, nullptr, AD, AD, W1N, 0, 0, 0);
        sw_reduce_kernel<<<Bb * NQ / 8, 256>>>(phs16, sw_W2 + (size_t)i * HD, sw_b2 + i, psm);
        // matrix update
        hgemm<5><<<dim3(8, 256, 1), 256, SMEM_BYTES>>>(
            phs16, pw16 + W_W2 + (size_t)i * D * MD, mw_b2 + (size_t)i * D, nullptr,
            pq16, pmat, pqm, MD, W1N, D, 0, 0, 0);
    }

    // final scan -> d_out (attn f32 straight to out_attn)
    attn_fused<<<Bb, 512, AT_SMEM>>>(pctx16, pqm, psm, pattn16, out_attn);
    hgemm<2><<<dim3(8, 2, Bb), 256, SMEM_BYTES>>>(
        pattn16, pctxT, nullptr, out_wc, nullptr, nullptr, nullptr,
        NC, NC, D, (size_t)NQ * NC, (size_t)NC * D, (size_t)NQ * D);

    cudaMemcpyAsync(out_q, query, (size_t)Bb * NQ * D * sizeof(float),
                    cudaMemcpyDeviceToDevice, 0);
}